// round 1
// baseline (speedup 1.0000x reference)
#include <cuda_runtime.h>
#include <cstdint>

// Problem constants
#define NN   200000
#define DM   500
#define BB   4096
#define MSG  1501        // 2*DM + 1 + DM
#define G3   1500        // 3*DM
#define ROWS 8192        // 2*B message rows

// Padded dims for the guard-free GEMM
#define KP1  1504        // msgs K padded (1501 -> 1504)
#define KP2  512         // h K padded (500 -> 512)
#define NP   1536        // GEMM N padded (1500 -> 1536)

// -------------------- scratch (device globals, no allocation) --------------------
__device__ float g_A1 [(size_t)ROWS * KP1];   // msgs rows, padded      (~49 MB)
__device__ float g_Wih[(size_t)NP   * KP1];   // zero-padded W_ih       (~9 MB)
__device__ float g_Whh[(size_t)NP   * KP2];   // zero-padded W_hh       (~3 MB)
__device__ float g_Gi [(size_t)ROWS * NP ];   // msgs @ W_ih^T          (~50 MB)
__device__ float g_Gh [(size_t)ROWS * NP ];   // h    @ W_hh^T          (~50 MB)
__device__ int   g_lastpos[NN];

// -------------------- helpers --------------------
__device__ __forceinline__ float sigf(float x) { return 1.0f / (1.0f + expf(-x)); }

// -------------------- copy kernels --------------------
__global__ void k_copy4(const float4* __restrict__ src, float4* __restrict__ dst, int n4) {
    int i = blockIdx.x * blockDim.x + threadIdx.x;
    if (i < n4) dst[i] = src[i];
}

// -------------------- weight padding --------------------
__global__ void k_pad_w(const float* __restrict__ Wih, const float* __restrict__ Whh) {
    const int total1 = NP * KP1;
    const int total2 = NP * KP2;
    int idx = blockIdx.x * blockDim.x + threadIdx.x;
    if (idx < total1) {
        int r = idx / KP1, k = idx - r * KP1;
        g_Wih[idx] = (r < G3 && k < MSG) ? Wih[r * MSG + k] : 0.0f;
    } else if (idx < total1 + total2) {
        int j = idx - total1;
        int r = j / KP2, k = j - r * KP2;
        g_Whh[j] = (r < G3 && k < DM) ? Whh[r * DM + k] : 0.0f;
    }
}

// -------------------- build message matrix --------------------
__global__ void k_build_msgs(const float* __restrict__ memory,
                             const float* __restrict__ last_update,
                             const float* __restrict__ ef_table,
                             const float* __restrict__ times,
                             const float* __restrict__ time_w,
                             const float* __restrict__ time_b,
                             const int* __restrict__ src,
                             const int* __restrict__ dst,
                             const int* __restrict__ edge_idxs) {
    int i = blockIdx.x;                 // 0..8191
    int e = i & (BB - 1);
    bool srow = (i < BB);
    int a = srow ? src[e] : dst[e];     // node owning this message
    int b = srow ? dst[e] : src[e];
    float t  = times[e];
    float dt = t - last_update[a];
    float* row = &g_A1[(size_t)i * KP1];
    const float* ma = memory + (size_t)a * DM;
    const float* mb = memory + (size_t)b * DM;
    for (int j = threadIdx.x; j < DM; j += blockDim.x) {
        row[j]          = ma[j];
        row[DM + j]     = mb[j];
        row[2*DM+1 + j] = cosf(fmaf(dt, time_w[j], time_b[j]));
    }
    if (threadIdx.x == 0) {
        row[2*DM] = ef_table[edge_idxs[e]];
        row[1501] = 0.0f; row[1502] = 0.0f; row[1503] = 0.0f;
    }
}

// -------------------- last-message aggregation --------------------
__global__ void k_lp_init(const int* __restrict__ src, const int* __restrict__ dst) {
    int i = blockIdx.x * blockDim.x + threadIdx.x;
    if (i >= 2 * BB) return;
    int node = (i < BB) ? src[i] : dst[i - BB];
    g_lastpos[node] = -1;
}
__global__ void k_lp_max(const int* __restrict__ src, const int* __restrict__ dst) {
    int i = blockIdx.x * blockDim.x + threadIdx.x;
    if (i >= 2 * BB) return;
    int node = (i < BB) ? src[i] : dst[i - BB];
    atomicMax(&g_lastpos[node], i);
}

// -------------------- guard-free SGEMM: C = A @ W^T --------------------
// MODE 0: Gi = g_A1[8192,KP1] @ g_Wih[NP,KP1]^T    (K = KP1)
// MODE 1: Gh = g_A1[8192,KP2] @ g_Whh[NP,KP2]^T    (K = KP2; junk A cols * 0 weights)
template <int MODE>
__global__ void __launch_bounds__(256) k_sgemm() {
    const float* __restrict__ A  = g_A1;
    const int lda = KP1;
    const float* __restrict__ Bm = (MODE == 0) ? g_Wih : g_Whh;
    const int ldb = (MODE == 0) ? KP1 : KP2;
    float* __restrict__ C        = (MODE == 0) ? g_Gi : g_Gh;
    const int K = (MODE == 0) ? KP1 : KP2;

    __shared__ float As[8][128];
    __shared__ float Bs[8][128];

    int tid  = threadIdx.x;
    int row0 = blockIdx.y * 128;
    int col0 = blockIdx.x * 128;

    int lr = tid >> 1;            // 0..127
    int lk = (tid & 1) * 4;       // 0 or 4
    const float* Aload = A  + (size_t)(row0 + lr) * lda + lk;
    const float* Bload = Bm + (size_t)(col0 + lr) * ldb + lk;

    int ty = tid >> 4, tx = tid & 15;
    float acc[8][8];
    #pragma unroll
    for (int r = 0; r < 8; r++)
        #pragma unroll
        for (int c = 0; c < 8; c++) acc[r][c] = 0.0f;

    for (int k0 = 0; k0 < K; k0 += 8) {
        float4 av = *(const float4*)(Aload + k0);
        float4 bv = *(const float4*)(Bload + k0);
        As[lk+0][lr] = av.x; As[lk+1][lr] = av.y; As[lk+2][lr] = av.z; As[lk+3][lr] = av.w;
        Bs[lk+0][lr] = bv.x; Bs[lk+1][lr] = bv.y; Bs[lk+2][lr] = bv.z; Bs[lk+3][lr] = bv.w;
        __syncthreads();
        #pragma unroll
        for (int kk = 0; kk < 8; kk++) {
            float4 a0 = *(const float4*)&As[kk][ty * 8];
            float4 a1 = *(const float4*)&As[kk][ty * 8 + 4];
            float4 b0 = *(const float4*)&Bs[kk][tx * 8];
            float4 b1 = *(const float4*)&Bs[kk][tx * 8 + 4];
            float a[8] = {a0.x, a0.y, a0.z, a0.w, a1.x, a1.y, a1.z, a1.w};
            float b[8] = {b0.x, b0.y, b0.z, b0.w, b1.x, b1.y, b1.z, b1.w};
            #pragma unroll
            for (int r = 0; r < 8; r++)
                #pragma unroll
                for (int c = 0; c < 8; c++)
                    acc[r][c] = fmaf(a[r], b[c], acc[r][c]);
        }
        __syncthreads();
    }
    #pragma unroll
    for (int r = 0; r < 8; r++) {
        float* Cp = C + (size_t)(row0 + ty * 8 + r) * NP + col0 + tx * 8;
        float4 v0 = {acc[r][0], acc[r][1], acc[r][2], acc[r][3]};
        float4 v1 = {acc[r][4], acc[r][5], acc[r][6], acc[r][7]};
        *(float4*)Cp       = v0;
        *(float4*)(Cp + 4) = v1;
    }
}

// -------------------- GRU gates + scatter --------------------
__global__ void k_gru_scatter(const float* __restrict__ bih,
                              const float* __restrict__ bhh,
                              const float* __restrict__ times,
                              const int* __restrict__ src,
                              const int* __restrict__ dst,
                              float* __restrict__ out_mem,
                              float* __restrict__ out_lu) {
    int i = blockIdx.x;
    int e = i & (BB - 1);
    int node = (i < BB) ? src[e] : dst[e];
    if (g_lastpos[node] != i) return;      // only the last message per node writes
    const float* gi   = &g_Gi[(size_t)i * NP];
    const float* gh   = &g_Gh[(size_t)i * NP];
    const float* hrow = &g_A1[(size_t)i * KP1];   // first DM cols = memory[node]
    float* om = out_mem + (size_t)node * DM;
    for (int j = threadIdx.x; j < DM; j += blockDim.x) {
        float r = sigf(gi[j]        + bih[j]        + gh[j]        + bhh[j]);
        float z = sigf(gi[DM + j]   + bih[DM + j]   + gh[DM + j]   + bhh[DM + j]);
        float n = tanhf(gi[2*DM + j] + bih[2*DM + j] + r * (gh[2*DM + j] + bhh[2*DM + j]));
        float h = hrow[j];
        om[j] = (1.0f - z) * n + z * h;
    }
    if (threadIdx.x == 0) out_lu[node] = times[e];
}

// -------------------- edge-score MLP --------------------
__global__ void k_scores(const float* __restrict__ memory,
                         const float* __restrict__ ce,
                         const float* __restrict__ W1, const float* __restrict__ b1,
                         const float* __restrict__ W2, const float* __restrict__ b2,
                         const float* __restrict__ W3, const float* __restrict__ b3,
                         const int* __restrict__ src, const int* __restrict__ dst,
                         const int* __restrict__ neg, float* __restrict__ out) {
    __shared__ float xs[4 * DM];
    __shared__ float h1[80];
    __shared__ float h2[10];
    int blk = blockIdx.x;           // 0..8191  (pos block then neg block)
    int e = blk & (BB - 1);
    int s = src[e];
    int other = (blk < BB) ? dst[e] : neg[e];
    const float* p0 = memory + (size_t)s * DM;
    const float* p1 = ce     + (size_t)s * DM;
    const float* p2 = memory + (size_t)other * DM;
    const float* p3 = ce     + (size_t)other * DM;
    for (int j = threadIdx.x; j < DM; j += blockDim.x) {
        xs[j]          = p0[j];
        xs[DM + j]     = p1[j];
        xs[2*DM + j]   = p2[j];
        xs[3*DM + j]   = p3[j];
    }
    __syncthreads();
    if (threadIdx.x < 80) {
        float acc = b1[threadIdx.x];
        #pragma unroll 4
        for (int k = 0; k < 4 * DM; k++)
            acc = fmaf(xs[k], W1[k * 80 + threadIdx.x], acc);
        h1[threadIdx.x] = fmaxf(acc, 0.0f);
    }
    __syncthreads();
    if (threadIdx.x < 10) {
        float acc = b2[threadIdx.x];
        #pragma unroll
        for (int k = 0; k < 80; k++)
            acc = fmaf(h1[k], W2[k * 10 + threadIdx.x], acc);
        h2[threadIdx.x] = fmaxf(acc, 0.0f);
    }
    __syncthreads();
    if (threadIdx.x == 0) {
        float acc = b3[0];
        #pragma unroll
        for (int k = 0; k < 10; k++) acc = fmaf(h2[k], W3[k], acc);
        out[(blk < BB) ? e : (BB + e)] = acc;
    }
}

// -------------------- launcher --------------------
extern "C" void kernel_launch(void* const* d_in, const int* in_sizes, int n_in,
                              void* d_out, int out_size) {
    const float* memory      = (const float*)d_in[0];
    const float* last_update = (const float*)d_in[1];
    const float* comm_emb    = (const float*)d_in[2];
    const float* ef_table    = (const float*)d_in[3];
    const float* edge_times  = (const float*)d_in[4];
    const float* time_w      = (const float*)d_in[5];
    const float* time_b      = (const float*)d_in[6];
    const float* W_ih        = (const float*)d_in[7];
    const float* W_hh        = (const float*)d_in[8];
    const float* b_ih        = (const float*)d_in[9];
    const float* b_hh        = (const float*)d_in[10];
    const float* W1          = (const float*)d_in[11];
    const float* b1          = (const float*)d_in[12];
    const float* W2          = (const float*)d_in[13];
    const float* b2          = (const float*)d_in[14];
    const float* W3          = (const float*)d_in[15];
    const float* b3          = (const float*)d_in[16];
    const int*   src         = (const int*)d_in[17];
    const int*   dst         = (const int*)d_in[18];
    const int*   neg         = (const int*)d_in[19];
    const int*   edge_idxs   = (const int*)d_in[20];

    float* out      = (float*)d_out;
    float* out_sc   = out;                                   // score_pos[B], score_neg[B]
    float* out_mem  = out + 2 * BB;                          // new_memory [N*DM]
    float* out_lu   = out + 2 * BB + (size_t)NN * DM;        // new_last_update [N]

    // 1) copy memory -> out_mem (100M floats = 25M float4)
    {
        int n4 = (NN * DM) / 4;    // 25,000,000
        k_copy4<<<(n4 + 255) / 256, 256>>>((const float4*)memory, (float4*)out_mem, n4);
    }
    // 2) copy last_update -> out_lu (200000 floats = 50000 float4)
    {
        int n4 = NN / 4;
        k_copy4<<<(n4 + 255) / 256, 256>>>((const float4*)last_update, (float4*)out_lu, n4);
    }
    // 3) pad weights into guard-free buffers
    {
        int total = NP * KP1 + NP * KP2;
        k_pad_w<<<(total + 255) / 256, 256>>>(W_ih, W_hh);
    }
    // 4) build message matrix
    k_build_msgs<<<ROWS, 256>>>(memory, last_update, ef_table, edge_times,
                                time_w, time_b, src, dst, edge_idxs);
    // 5) last-message aggregation
    k_lp_init<<<(2 * BB + 255) / 256, 256>>>(src, dst);
    k_lp_max <<<(2 * BB + 255) / 256, 256>>>(src, dst);
    // 6) GRU GEMMs
    {
        dim3 grid(NP / 128, ROWS / 128);   // (12, 64)
        k_sgemm<0><<<grid, 256>>>();
        k_sgemm<1><<<grid, 256>>>();
    }
    // 7) edge scores (independent)
    k_scores<<<2 * BB, 128>>>(memory, comm_emb, W1, b1, W2, b2, W3, b3,
                              src, dst, neg, out_sc);
    // 8) gates + scatter (after copy + gemms + lp_max)
    k_gru_scatter<<<ROWS, 512>>>(b_ih, b_hh, edge_times, src, dst, out_mem, out_lu);
}

// round 7
// speedup vs baseline: 2.5547x; 2.5547x over previous
#include <cuda_runtime.h>
#include <cuda_bf16.h>
#include <cstdint>

// Problem constants
#define NN   200000
#define DM   500
#define BB   4096
#define MSG  1501        // 2*DM + 1 + DM
#define G3   1500        // 3*DM
#define ROWS 8192        // 2*B message rows

// Padded dims for guard-free GEMMs
#define KP1  1504        // msgs K padded (1501 -> 1504, mult of 32)
#define KP2  512         // h K padded (500 -> 512)
#define NP   1536        // GRU GEMM N padded (1500 -> 1536)
#define KX   2048        // score layer-1 K padded (4 segments of 512)
#define NX   128         // score layer-1 N padded (80 -> 128)

typedef __nv_bfloat16 bf16;

// -------------------- scratch (device globals, no allocation) --------------------
// NOTE: these are ONLY referenced from device code (never passed as kernel
// arguments from host — host-side symbol names are host-shadow addresses,
// which GB300's ATS dereferences silently into host memory).
__device__ __align__(128) bf16 g_A1h [(size_t)ROWS * KP1];
__device__ __align__(128) bf16 g_A1l [(size_t)ROWS * KP1];
__device__ __align__(128) bf16 g_Wihh[(size_t)NP   * KP1];
__device__ __align__(128) bf16 g_Wihl[(size_t)NP   * KP1];
__device__ __align__(128) bf16 g_Whhh[(size_t)NP   * KP2];
__device__ __align__(128) bf16 g_Whhl[(size_t)NP   * KP2];
__device__ __align__(128) bf16 g_Xph [(size_t)ROWS * KX ];
__device__ __align__(128) bf16 g_Xpl [(size_t)ROWS * KX ];
__device__ __align__(128) bf16 g_W1ph[(size_t)NX   * KX ];
__device__ __align__(128) bf16 g_W1pl[(size_t)NX   * KX ];
__device__ __align__(128) float g_Gi [(size_t)ROWS * NP ];
__device__ __align__(128) float g_Gh [(size_t)ROWS * NP ];
__device__ __align__(128) float g_H1 [(size_t)ROWS * NX ];
__device__ int g_lastpos[NN];

// -------------------- helpers --------------------
__device__ __forceinline__ float sigf(float x) { return 1.0f / (1.0f + expf(-x)); }
__device__ __forceinline__ void split_bf16(float x, bf16* ph, bf16* pl) {
    bf16 h = __float2bfloat16_rn(x);
    bf16 l = __float2bfloat16_rn(x - __bfloat162float(h));
    *ph = h; *pl = l;
}

// -------------------- copy kernel --------------------
__global__ void k_copy4(const float4* __restrict__ src, float4* __restrict__ dst, int n4) {
    int i = blockIdx.x * blockDim.x + threadIdx.x;
    if (i < n4) dst[i] = src[i];
}

// -------------------- weight padding (split bf16) --------------------
__global__ void k_pad_w(const float* __restrict__ Wih, const float* __restrict__ Whh) {
    const int total1 = NP * KP1;
    const int total2 = NP * KP2;
    int idx = blockIdx.x * blockDim.x + threadIdx.x;
    if (idx < total1) {
        int r = idx / KP1, k = idx - r * KP1;
        float v = (r < G3 && k < MSG) ? Wih[r * MSG + k] : 0.0f;
        split_bf16(v, &g_Wihh[idx], &g_Wihl[idx]);
    } else if (idx < total1 + total2) {
        int j = idx - total1;
        int r = j / KP2, k = j - r * KP2;
        float v = (r < G3 && k < DM) ? Whh[r * DM + k] : 0.0f;
        split_bf16(v, &g_Whhh[j], &g_Whhl[j]);
    }
}

__global__ void k_pad_w1(const float* __restrict__ W1) {
    int idx = blockIdx.x * blockDim.x + threadIdx.x;   // NX * KX
    if (idx >= NX * KX) return;
    int n = idx >> 11, k = idx & (KX - 1);
    int seg = k >> 9, j = k & 511;
    float v = 0.0f;
    if (n < 80 && j < DM) v = W1[(seg * DM + j) * 80 + n];
    split_bf16(v, &g_W1ph[idx], &g_W1pl[idx]);
}

// -------------------- build message matrix (split bf16) --------------------
__global__ void k_build_msgs(const float* __restrict__ memory,
                             const float* __restrict__ last_update,
                             const float* __restrict__ ef_table,
                             const float* __restrict__ times,
                             const float* __restrict__ time_w,
                             const float* __restrict__ time_b,
                             const int* __restrict__ src,
                             const int* __restrict__ dst,
                             const int* __restrict__ edge_idxs) {
    int i = blockIdx.x;                 // 0..8191
    int e = i & (BB - 1);
    bool srow = (i < BB);
    int a = srow ? src[e] : dst[e];     // node owning this message
    int b = srow ? dst[e] : src[e];
    float t  = times[e];
    float dt = t - last_update[a];
    size_t ro = (size_t)i * KP1;
    const float* ma = memory + (size_t)a * DM;
    const float* mb = memory + (size_t)b * DM;
    for (int j = threadIdx.x; j < DM; j += blockDim.x) {
        split_bf16(ma[j], &g_A1h[ro + j],          &g_A1l[ro + j]);
        split_bf16(mb[j], &g_A1h[ro + DM + j],     &g_A1l[ro + DM + j]);
        float enc = cosf(fmaf(dt, time_w[j], time_b[j]));
        split_bf16(enc,   &g_A1h[ro + 2*DM+1 + j], &g_A1l[ro + 2*DM+1 + j]);
    }
    if (threadIdx.x == 0) {
        split_bf16(ef_table[edge_idxs[e]], &g_A1h[ro + 2*DM], &g_A1l[ro + 2*DM]);
        for (int p = MSG; p < KP1; p++) { g_A1h[ro + p] = __float2bfloat16(0.f); g_A1l[ro + p] = __float2bfloat16(0.f); }
    }
}

// -------------------- build score-MLP input matrix --------------------
__global__ void k_build_X(const float* __restrict__ memory,
                          const float* __restrict__ ce,
                          const int* __restrict__ src,
                          const int* __restrict__ dst,
                          const int* __restrict__ neg) {
    int i = blockIdx.x;                 // 0..8191
    int e = i & (BB - 1);
    int s = src[e];
    int o = (i < BB) ? dst[e] : neg[e];
    size_t ro = (size_t)i * KX;
    const float* seg0 = memory + (size_t)s * DM;
    const float* seg1 = ce     + (size_t)s * DM;
    const float* seg2 = memory + (size_t)o * DM;
    const float* seg3 = ce     + (size_t)o * DM;
    for (int k = threadIdx.x; k < KX; k += blockDim.x) {
        int seg = k >> 9, j = k & 511;
        float v = 0.0f;
        if (j < DM) {
            const float* p = (seg == 0) ? seg0 : (seg == 1) ? seg1 : (seg == 2) ? seg2 : seg3;
            v = p[j];
        }
        split_bf16(v, &g_Xph[ro + k], &g_Xpl[ro + k]);
    }
}

// -------------------- last-message aggregation --------------------
__global__ void k_lp_init(const int* __restrict__ src, const int* __restrict__ dst) {
    int i = blockIdx.x * blockDim.x + threadIdx.x;
    if (i >= 2 * BB) return;
    int node = (i < BB) ? src[i] : dst[i - BB];
    g_lastpos[node] = -1;
}
__global__ void k_lp_max(const int* __restrict__ src, const int* __restrict__ dst) {
    int i = blockIdx.x * blockDim.x + threadIdx.x;
    if (i >= 2 * BB) return;
    int node = (i < BB) ? src[i] : dst[i - BB];
    atomicMax(&g_lastpos[node], i);
}

// -------------------- split-bf16 tensor-core GEMM: C = A @ B^T --------------------
// All operands are device globals selected by MODE (never passed from host!).
// C = Ah*Bh + Ah*Bl + Al*Bh  (fp32 accumulate) — ~1e-5 relative accuracy.
// BM=64, BN=64, BK=32 elements, double-buffered cp.async, mma.m16n8k16.bf16.
#define SSTW 20                  // smem row stride in words (16 data + 4 pad)
#define SMSW (64 * SSTW)

#define MMA_BF16(ACC, A_, B_) \
    asm volatile("mma.sync.aligned.m16n8k16.row.col.f32.bf16.bf16.f32 " \
        "{%0,%1,%2,%3}, {%4,%5,%6,%7}, {%8,%9}, {%0,%1,%2,%3};" \
        : "+f"((ACC)[0]), "+f"((ACC)[1]), "+f"((ACC)[2]), "+f"((ACC)[3]) \
        : "r"((A_)[0]), "r"((A_)[1]), "r"((A_)[2]), "r"((A_)[3]), \
          "r"((B_)[0]), "r"((B_)[1]))

template <int MODE>
__global__ void __launch_bounds__(128) k_mma() {
    const bf16* __restrict__ Ah = (MODE == 2) ? g_Xph : g_A1h;
    const bf16* __restrict__ Al = (MODE == 2) ? g_Xpl : g_A1l;
    const int lda               = (MODE == 2) ? KX : KP1;
    const bf16* __restrict__ Bh = (MODE == 0) ? g_Wihh : (MODE == 1) ? g_Whhh : g_W1ph;
    const bf16* __restrict__ Bl = (MODE == 0) ? g_Wihl : (MODE == 1) ? g_Whhl : g_W1pl;
    const int ldb               = (MODE == 0) ? KP1 : (MODE == 1) ? KP2 : KX;
    float* __restrict__ C       = (MODE == 0) ? g_Gi : (MODE == 1) ? g_Gh : g_H1;
    const int ldc               = (MODE == 2) ? NX : NP;
    const int K                 = ldb;   // B is [N x K] with row stride == K

    __shared__ __align__(16) uint32_t sm[2][4][SMSW];   // 40,960 B

    const int tid  = threadIdx.x;
    const int lane = tid & 31;
    const int wid  = tid >> 5;          // 0..3
    const int wm   = wid >> 1;          // 0..1
    const int wn   = wid & 1;           // 0..1
    const int q    = lane >> 2;         // 0..7
    const int rr   = lane & 3;          // 0..3

    const int row0 = blockIdx.y * 64;
    const int col0 = blockIdx.x * 64;

    float acc[2][4][4];
    #pragma unroll
    for (int am = 0; am < 2; am++)
        #pragma unroll
        for (int bn = 0; bn < 4; bn++)
            #pragma unroll
            for (int c = 0; c < 4; c++) acc[am][bn][c] = 0.0f;

    const int K_tiles = K >> 5;

    auto load_stage = [&](int stage, int k0) {
        #pragma unroll
        for (int i = 0; i < 2; i++) {
            int f  = i * 128 + tid;      // 0..255
            int r  = f >> 2;             // 0..63
            int w4 = (f & 3) * 4;        // word offset: 0,4,8,12
            int eo = k0 + w4 * 2;        // element offset in row
            const bf16* pAh = Ah + (size_t)(row0 + r) * lda + eo;
            const bf16* pAl = Al + (size_t)(row0 + r) * lda + eo;
            const bf16* pBh = Bh + (size_t)(col0 + r) * ldb + eo;
            const bf16* pBl = Bl + (size_t)(col0 + r) * ldb + eo;
            uint32_t s0 = (uint32_t)__cvta_generic_to_shared(&sm[stage][0][r * SSTW + w4]);
            uint32_t s1 = (uint32_t)__cvta_generic_to_shared(&sm[stage][1][r * SSTW + w4]);
            uint32_t s2 = (uint32_t)__cvta_generic_to_shared(&sm[stage][2][r * SSTW + w4]);
            uint32_t s3 = (uint32_t)__cvta_generic_to_shared(&sm[stage][3][r * SSTW + w4]);
            asm volatile("cp.async.cg.shared.global [%0], [%1], 16;" :: "r"(s0), "l"(pAh));
            asm volatile("cp.async.cg.shared.global [%0], [%1], 16;" :: "r"(s1), "l"(pAl));
            asm volatile("cp.async.cg.shared.global [%0], [%1], 16;" :: "r"(s2), "l"(pBh));
            asm volatile("cp.async.cg.shared.global [%0], [%1], 16;" :: "r"(s3), "l"(pBl));
        }
        asm volatile("cp.async.commit_group;");
    };

    load_stage(0, 0);

    for (int t = 0; t < K_tiles; t++) {
        int s = t & 1;
        if (t + 1 < K_tiles) {
            load_stage((t + 1) & 1, (t + 1) << 5);
            asm volatile("cp.async.wait_group 1;");
        } else {
            asm volatile("cp.async.wait_group 0;");
        }
        __syncthreads();

        const uint32_t* Ash = sm[s][0];
        const uint32_t* Asl = sm[s][1];
        const uint32_t* Bsh = sm[s][2];
        const uint32_t* Bsl = sm[s][3];

        #pragma unroll
        for (int kk = 0; kk < 2; kk++) {            // two k16 steps per 32-elem tile
            int kw = kk * 8 + rr;                   // word index within row
            uint32_t ah[2][4], al[2][4], bh[4][2], bl[4][2];
            #pragma unroll
            for (int am = 0; am < 2; am++) {
                int base = (wm * 32 + am * 16 + q) * SSTW + kw;
                ah[am][0] = Ash[base];              al[am][0] = Asl[base];
                ah[am][1] = Ash[base + 8 * SSTW];   al[am][1] = Asl[base + 8 * SSTW];
                ah[am][2] = Ash[base + 4];          al[am][2] = Asl[base + 4];
                ah[am][3] = Ash[base + 8*SSTW + 4]; al[am][3] = Asl[base + 8*SSTW + 4];
            }
            #pragma unroll
            for (int bn = 0; bn < 4; bn++) {
                int base = (wn * 32 + bn * 8 + q) * SSTW + kw;
                bh[bn][0] = Bsh[base];     bl[bn][0] = Bsl[base];
                bh[bn][1] = Bsh[base + 4]; bl[bn][1] = Bsl[base + 4];
            }
            #pragma unroll
            for (int am = 0; am < 2; am++)
                #pragma unroll
                for (int bn = 0; bn < 4; bn++) {
                    MMA_BF16(acc[am][bn], ah[am], bh[bn]);
                    MMA_BF16(acc[am][bn], ah[am], bl[bn]);
                    MMA_BF16(acc[am][bn], al[am], bh[bn]);
                }
        }
        __syncthreads();
    }

    // epilogue
    #pragma unroll
    for (int am = 0; am < 2; am++) {
        int r = row0 + wm * 32 + am * 16 + q;
        #pragma unroll
        for (int bn = 0; bn < 4; bn++) {
            int c = col0 + wn * 32 + bn * 8 + rr * 2;
            float2 v0 = {acc[am][bn][0], acc[am][bn][1]};
            float2 v1 = {acc[am][bn][2], acc[am][bn][3]};
            *(float2*)&C[(size_t)r * ldc + c]       = v0;
            *(float2*)&C[(size_t)(r + 8) * ldc + c] = v1;
        }
    }
}

// -------------------- GRU gates + scatter --------------------
__global__ void k_gru_scatter(const float* __restrict__ memory,
                              const float* __restrict__ bih,
                              const float* __restrict__ bhh,
                              const float* __restrict__ times,
                              const int* __restrict__ src,
                              const int* __restrict__ dst,
                              float* __restrict__ out_mem,
                              float* __restrict__ out_lu) {
    int i = blockIdx.x;
    int e = i & (BB - 1);
    int node = (i < BB) ? src[e] : dst[e];
    if (g_lastpos[node] != i) return;      // only the last message per node writes
    const float* gi   = &g_Gi[(size_t)i * NP];
    const float* gh   = &g_Gh[(size_t)i * NP];
    const float* hrow = memory + (size_t)node * DM;   // exact fp32 h
    float* om = out_mem + (size_t)node * DM;
    for (int j = threadIdx.x; j < DM; j += blockDim.x) {
        float r = sigf(gi[j]        + bih[j]        + gh[j]        + bhh[j]);
        float z = sigf(gi[DM + j]   + bih[DM + j]   + gh[DM + j]   + bhh[DM + j]);
        float n = tanhf(gi[2*DM + j] + bih[2*DM + j] + r * (gh[2*DM + j] + bhh[2*DM + j]));
        float h = hrow[j];
        om[j] = (1.0f - z) * n + z * h;
    }
    if (threadIdx.x == 0) out_lu[node] = times[e];
}

// -------------------- score MLP tail (layers 2, 3) --------------------
__global__ void k_scores_tail(const float* __restrict__ b1,
                              const float* __restrict__ W2, const float* __restrict__ b2,
                              const float* __restrict__ W3, const float* __restrict__ b3,
                              float* __restrict__ out) {
    __shared__ float sW2[80 * 10];
    __shared__ float sW3[10];
    __shared__ float sb1[80];
    __shared__ float sb2[10];
    int tid = threadIdx.x;
    if (tid < 80) sb1[tid] = b1[tid];
    if (tid >= 128 && tid < 128 + 10) { sW3[tid - 128] = W3[tid - 128]; sb2[tid - 128] = b2[tid - 128]; }
    for (int j = tid; j < 800; j += blockDim.x) sW2[j] = W2[j];
    __syncthreads();

    int i = blockIdx.x * blockDim.x + tid;    // 0..8191
    const float* h1row = &g_H1[(size_t)i * NX];
    float h1[80];
    #pragma unroll 8
    for (int j = 0; j < 80; j++) h1[j] = fmaxf(h1row[j] + sb1[j], 0.0f);
    float sc = b3[0];
    #pragma unroll
    for (int c = 0; c < 10; c++) {
        float h2 = sb2[c];
        #pragma unroll 8
        for (int j = 0; j < 80; j++) h2 = fmaf(h1[j], sW2[j * 10 + c], h2);
        sc = fmaf(fmaxf(h2, 0.0f), sW3[c], sc);
    }
    out[i] = sc;    // rows 0..B-1 = score_pos, B..2B-1 = score_neg
}

// -------------------- launcher --------------------
extern "C" void kernel_launch(void* const* d_in, const int* in_sizes, int n_in,
                              void* d_out, int out_size) {
    const float* memory      = (const float*)d_in[0];
    const float* last_update = (const float*)d_in[1];
    const float* comm_emb    = (const float*)d_in[2];
    const float* ef_table    = (const float*)d_in[3];
    const float* edge_times  = (const float*)d_in[4];
    const float* time_w      = (const float*)d_in[5];
    const float* time_b      = (const float*)d_in[6];
    const float* W_ih        = (const float*)d_in[7];
    const float* W_hh        = (const float*)d_in[8];
    const float* b_ih        = (const float*)d_in[9];
    const float* b_hh        = (const float*)d_in[10];
    const float* W1          = (const float*)d_in[11];
    const float* b1          = (const float*)d_in[12];
    const float* W2          = (const float*)d_in[13];
    const float* b2          = (const float*)d_in[14];
    const float* W3          = (const float*)d_in[15];
    const float* b3          = (const float*)d_in[16];
    const int*   src         = (const int*)d_in[17];
    const int*   dst         = (const int*)d_in[18];
    const int*   neg         = (const int*)d_in[19];
    const int*   edge_idxs   = (const int*)d_in[20];

    float* out      = (float*)d_out;
    float* out_sc   = out;                                   // score_pos[B], score_neg[B]
    float* out_mem  = out + 2 * BB;                          // new_memory [N*DM]
    float* out_lu   = out + 2 * BB + (size_t)NN * DM;        // new_last_update [N]

    // 1) copy memory -> out_mem
    {
        int n4 = (NN * DM) / 4;
        k_copy4<<<(n4 + 255) / 256, 256>>>((const float4*)memory, (float4*)out_mem, n4);
    }
    // 2) copy last_update -> out_lu
    {
        int n4 = NN / 4;
        k_copy4<<<(n4 + 255) / 256, 256>>>((const float4*)last_update, (float4*)out_lu, n4);
    }
    // 3) pad/split weights
    {
        int total = NP * KP1 + NP * KP2;
        k_pad_w<<<(total + 255) / 256, 256>>>(W_ih, W_hh);
        k_pad_w1<<<(NX * KX + 255) / 256, 256>>>(W1);
    }
    // 4) build message matrix + score input matrix (split bf16)
    k_build_msgs<<<ROWS, 256>>>(memory, last_update, ef_table, edge_times,
                                time_w, time_b, src, dst, edge_idxs);
    k_build_X<<<ROWS, 256>>>(memory, comm_emb, src, dst, neg);
    // 5) last-message aggregation
    k_lp_init<<<(2 * BB + 255) / 256, 256>>>(src, dst);
    k_lp_max <<<(2 * BB + 255) / 256, 256>>>(src, dst);
    // 6) split-bf16 tensor-core GEMMs (operands bound in device code)
    {
        dim3 g1(NP / 64, ROWS / 64);       // (24, 128)
        k_mma<0><<<g1, 128>>>();
        k_mma<1><<<g1, 128>>>();
        dim3 g2(NX / 64, ROWS / 64);       // (2, 128)
        k_mma<2><<<g2, 128>>>();
    }
    // 7) score MLP tail
    k_scores_tail<<<ROWS / 256, 256>>>(b1, W2, b2, W3, b3, out_sc);
    // 8) gates + scatter
    k_gru_scatter<<<ROWS, 512>>>(memory, b_ih, b_hh, edge_times, src, dst, out_mem, out_lu);
}

// round 10
// speedup vs baseline: 3.2561x; 1.2746x over previous
#include <cuda_runtime.h>
#include <cuda_fp16.h>
#include <cstdint>

// Problem constants
#define NN   200000
#define DM   500
#define BB   4096
#define MSG  1501        // 2*DM + 1 + DM
#define G3   1500        // 3*DM
#define ROWS 8192        // 2*B message rows

// Padded dims for guard-free GEMMs
#define KP1  1504        // msgs K padded (1501 -> 1504, mult of 32)
#define KP2  512         // h K padded (500 -> 512)
#define NP   1536        // GRU GEMM N padded (1500 -> 1536)
#define KX   2048        // score layer-1 K padded (4 segments of 512)
#define NX   128         // score layer-1 N padded (80 -> 128)

typedef __half fp16;

// -------------------- scratch (device globals, no allocation) --------------------
// ONLY referenced from device code (host-side symbol name = host shadow addr,
// silently dereferenced via ATS on GB300 — round 2-4 bug).
__device__ __align__(128) fp16 g_A1  [(size_t)ROWS * KP1];   // msgs, fp16 (A unsplit)
__device__ __align__(128) fp16 g_Wihh[(size_t)NP   * KP1];
__device__ __align__(128) fp16 g_Wihl[(size_t)NP   * KP1];
__device__ __align__(128) fp16 g_Whhh[(size_t)NP   * KP2];
__device__ __align__(128) fp16 g_Whhl[(size_t)NP   * KP2];
__device__ __align__(128) fp16 g_Xp  [(size_t)ROWS * KX ];
__device__ __align__(128) fp16 g_W1ph[(size_t)NX   * KX ];
__device__ __align__(128) fp16 g_W1pl[(size_t)NX   * KX ];
__device__ __align__(128) float g_Gi [(size_t)ROWS * NP ];
__device__ __align__(128) float g_Gh [(size_t)ROWS * NP ];
__device__ __align__(128) float g_H1 [(size_t)ROWS * NX ];
__device__ int g_lastpos[NN];

// -------------------- helpers --------------------
__device__ __forceinline__ float sigf(float x) { return 1.0f / (1.0f + expf(-x)); }
__device__ __forceinline__ void split_fp16(float x, fp16* ph, fp16* pl) {
    fp16 h = __float2half_rn(x);
    fp16 l = __float2half_rn(x - __half2float(h));
    *ph = h; *pl = l;
}

// -------------------- copy kernel --------------------
__global__ void k_copy4(const float4* __restrict__ src, float4* __restrict__ dst, int n4) {
    int i = blockIdx.x * blockDim.x + threadIdx.x;
    if (i < n4) dst[i] = src[i];
}

// -------------------- weight padding (split fp16) --------------------
__global__ void k_pad_w(const float* __restrict__ Wih, const float* __restrict__ Whh) {
    const int total1 = NP * KP1;
    const int total2 = NP * KP2;
    int idx = blockIdx.x * blockDim.x + threadIdx.x;
    if (idx < total1) {
        int r = idx / KP1, k = idx - r * KP1;
        float v = (r < G3 && k < MSG) ? Wih[r * MSG + k] : 0.0f;
        split_fp16(v, &g_Wihh[idx], &g_Wihl[idx]);
    } else if (idx < total1 + total2) {
        int j = idx - total1;
        int r = j / KP2, k = j - r * KP2;
        float v = (r < G3 && k < DM) ? Whh[r * DM + k] : 0.0f;
        split_fp16(v, &g_Whhh[j], &g_Whhl[j]);
    }
}

__global__ void k_pad_w1(const float* __restrict__ W1) {
    int idx = blockIdx.x * blockDim.x + threadIdx.x;   // NX * KX
    if (idx >= NX * KX) return;
    int n = idx >> 11, k = idx & (KX - 1);
    int seg = k >> 9, j = k & 511;
    float v = 0.0f;
    if (n < 80 && j < DM) v = W1[(seg * DM + j) * 80 + n];
    split_fp16(v, &g_W1ph[idx], &g_W1pl[idx]);
}

// -------------------- build message matrix (fp16) --------------------
__global__ void k_build_msgs(const float* __restrict__ memory,
                             const float* __restrict__ last_update,
                             const float* __restrict__ ef_table,
                             const float* __restrict__ times,
                             const float* __restrict__ time_w,
                             const float* __restrict__ time_b,
                             const int* __restrict__ src,
                             const int* __restrict__ dst,
                             const int* __restrict__ edge_idxs) {
    int i = blockIdx.x;                 // 0..8191
    int e = i & (BB - 1);
    bool srow = (i < BB);
    int a = srow ? src[e] : dst[e];     // node owning this message
    int b = srow ? dst[e] : src[e];
    float t  = times[e];
    float dt = t - last_update[a];
    size_t ro = (size_t)i * KP1;
    const float* ma = memory + (size_t)a * DM;
    const float* mb = memory + (size_t)b * DM;
    for (int j = threadIdx.x; j < DM; j += blockDim.x) {
        g_A1[ro + j]          = __float2half_rn(ma[j]);
        g_A1[ro + DM + j]     = __float2half_rn(mb[j]);
        float enc = cosf(fmaf(dt, time_w[j], time_b[j]));
        g_A1[ro + 2*DM+1 + j] = __float2half_rn(enc);
    }
    if (threadIdx.x == 0) {
        g_A1[ro + 2*DM] = __float2half_rn(ef_table[edge_idxs[e]]);
        for (int p = MSG; p < KP1; p++) g_A1[ro + p] = __float2half_rn(0.f);
    }
}

// -------------------- build score-MLP input matrix --------------------
__global__ void k_build_X(const float* __restrict__ memory,
                          const float* __restrict__ ce,
                          const int* __restrict__ src,
                          const int* __restrict__ dst,
                          const int* __restrict__ neg) {
    int i = blockIdx.x;                 // 0..8191
    int e = i & (BB - 1);
    int s = src[e];
    int o = (i < BB) ? dst[e] : neg[e];
    size_t ro = (size_t)i * KX;
    const float* seg0 = memory + (size_t)s * DM;
    const float* seg1 = ce     + (size_t)s * DM;
    const float* seg2 = memory + (size_t)o * DM;
    const float* seg3 = ce     + (size_t)o * DM;
    for (int k = threadIdx.x; k < KX; k += blockDim.x) {
        int seg = k >> 9, j = k & 511;
        float v = 0.0f;
        if (j < DM) {
            const float* p = (seg == 0) ? seg0 : (seg == 1) ? seg1 : (seg == 2) ? seg2 : seg3;
            v = p[j];
        }
        g_Xp[ro + k] = __float2half_rn(v);
    }
}

// -------------------- last-message aggregation --------------------
__global__ void k_lp_init(const int* __restrict__ src, const int* __restrict__ dst) {
    int i = blockIdx.x * blockDim.x + threadIdx.x;
    if (i >= 2 * BB) return;
    int node = (i < BB) ? src[i] : dst[i - BB];
    g_lastpos[node] = -1;
}
__global__ void k_lp_max(const int* __restrict__ src, const int* __restrict__ dst) {
    int i = blockIdx.x * blockDim.x + threadIdx.x;
    if (i >= 2 * BB) return;
    int node = (i < BB) ? src[i] : dst[i - BB];
    atomicMax(&g_lastpos[node], i);
}

// -------------------- split-fp16 tensor-core GEMM: C = A @ B^T --------------------
// C = Ah*Bh + Ah*Bl (fp32 accumulate). A rounded once to fp16, B split h/l.
// BM=128, BN=64, BK=32, 256 threads (8 warps, 32x32 warp tiles),
// double-buffered cp.async, mma.m16n8k16.f16.
#define SSTW 20                  // smem row stride in words (16 data + 4 pad)

#define MMA_FP16(ACC, A_, B_) \
    asm volatile("mma.sync.aligned.m16n8k16.row.col.f32.f16.f16.f32 " \
        "{%0,%1,%2,%3}, {%4,%5,%6,%7}, {%8,%9}, {%0,%1,%2,%3};" \
        : "+f"((ACC)[0]), "+f"((ACC)[1]), "+f"((ACC)[2]), "+f"((ACC)[3]) \
        : "r"((A_)[0]), "r"((A_)[1]), "r"((A_)[2]), "r"((A_)[3]), \
          "r"((B_)[0]), "r"((B_)[1]))

template <int MODE>
__global__ void __launch_bounds__(256) k_mma() {
    const fp16* __restrict__ A  = (MODE == 2) ? g_Xp : g_A1;
    const int lda               = (MODE == 2) ? KX : KP1;
    const fp16* __restrict__ Bh = (MODE == 0) ? g_Wihh : (MODE == 1) ? g_Whhh : g_W1ph;
    const fp16* __restrict__ Bl = (MODE == 0) ? g_Wihl : (MODE == 1) ? g_Whhl : g_W1pl;
    const int ldb               = (MODE == 0) ? KP1 : (MODE == 1) ? KP2 : KX;
    float* __restrict__ C       = (MODE == 0) ? g_Gi : (MODE == 1) ? g_Gh : g_H1;
    const int ldc               = (MODE == 2) ? NX : NP;
    const int K                 = ldb;   // B is [N x K] with row stride == K

    __shared__ __align__(16) uint32_t smA [2][128 * SSTW];   // 20 KB
    __shared__ __align__(16) uint32_t smBh[2][ 64 * SSTW];   // 10 KB
    __shared__ __align__(16) uint32_t smBl[2][ 64 * SSTW];   // 10 KB

    const int tid  = threadIdx.x;
    const int lane = tid & 31;
    const int wid  = tid >> 5;          // 0..7
    const int wm   = wid >> 1;          // 0..3 -> 32-row slice of 128
    const int wn   = wid & 1;           // 0..1 -> 32-col slice of 64
    const int q    = lane >> 2;         // 0..7
    const int rr   = lane & 3;          // 0..3

    const int row0 = blockIdx.y * 128;
    const int col0 = blockIdx.x * 64;

    float acc[2][4][4];
    #pragma unroll
    for (int am = 0; am < 2; am++)
        #pragma unroll
        for (int bn = 0; bn < 4; bn++)
            #pragma unroll
            for (int c = 0; c < 4; c++) acc[am][bn][c] = 0.0f;

    const int K_tiles = K >> 5;

    auto load_stage = [&](int stage, int k0) {
        // A tile: 128 rows x 32 fp16 = 512 x 16B chunks; 256 thr -> 2 each
        #pragma unroll
        for (int i = 0; i < 2; i++) {
            int f  = i * 256 + tid;      // 0..511
            int r  = f >> 2;             // 0..127
            int w4 = (f & 3) * 4;        // word offset 0,4,8,12
            const fp16* gp = A + (size_t)(row0 + r) * lda + k0 + w4 * 2;
            uint32_t sp = (uint32_t)__cvta_generic_to_shared(&smA[stage][r * SSTW + w4]);
            asm volatile("cp.async.cg.shared.global [%0], [%1], 16;" :: "r"(sp), "l"(gp));
        }
        // B tiles: 64 rows x 32 fp16 = 256 chunks each
        {
            int r  = tid >> 2;           // 0..63
            int w4 = (tid & 3) * 4;
            int eo = k0 + w4 * 2;
            const fp16* gph = Bh + (size_t)(col0 + r) * ldb + eo;
            const fp16* gpl = Bl + (size_t)(col0 + r) * ldb + eo;
            uint32_t sph = (uint32_t)__cvta_generic_to_shared(&smBh[stage][r * SSTW + w4]);
            uint32_t spl = (uint32_t)__cvta_generic_to_shared(&smBl[stage][r * SSTW + w4]);
            asm volatile("cp.async.cg.shared.global [%0], [%1], 16;" :: "r"(sph), "l"(gph));
            asm volatile("cp.async.cg.shared.global [%0], [%1], 16;" :: "r"(spl), "l"(gpl));
        }
        asm volatile("cp.async.commit_group;");
    };

    load_stage(0, 0);

    for (int t = 0; t < K_tiles; t++) {
        int s = t & 1;
        if (t + 1 < K_tiles) {
            load_stage((t + 1) & 1, (t + 1) << 5);
            asm volatile("cp.async.wait_group 1;");
        } else {
            asm volatile("cp.async.wait_group 0;");
        }
        __syncthreads();

        const uint32_t* As  = smA [s];
        const uint32_t* Bsh = smBh[s];
        const uint32_t* Bsl = smBl[s];

        #pragma unroll
        for (int kk = 0; kk < 2; kk++) {            // two k16 steps per 32-elem tile
            int kw = kk * 8 + rr;                   // word index within row
            uint32_t a[2][4], bh[4][2], bl[4][2];
            #pragma unroll
            for (int am = 0; am < 2; am++) {
                int base = (wm * 32 + am * 16 + q) * SSTW + kw;
                a[am][0] = As[base];
                a[am][1] = As[base + 8 * SSTW];
                a[am][2] = As[base + 4];
                a[am][3] = As[base + 8 * SSTW + 4];
            }
            #pragma unroll
            for (int bn = 0; bn < 4; bn++) {
                int base = (wn * 32 + bn * 8 + q) * SSTW + kw;
                bh[bn][0] = Bsh[base];     bl[bn][0] = Bsl[base];
                bh[bn][1] = Bsh[base + 4]; bl[bn][1] = Bsl[base + 4];
            }
            #pragma unroll
            for (int am = 0; am < 2; am++)
                #pragma unroll
                for (int bn = 0; bn < 4; bn++) {
                    MMA_FP16(acc[am][bn], a[am], bh[bn]);
                    MMA_FP16(acc[am][bn], a[am], bl[bn]);
                }
        }
        __syncthreads();
    }

    // epilogue
    #pragma unroll
    for (int am = 0; am < 2; am++) {
        int r = row0 + wm * 32 + am * 16 + q;
        #pragma unroll
        for (int bn = 0; bn < 4; bn++) {
            int c = col0 + wn * 32 + bn * 8 + rr * 2;
            float2 v0 = {acc[am][bn][0], acc[am][bn][1]};
            float2 v1 = {acc[am][bn][2], acc[am][bn][3]};
            *(float2*)&C[(size_t)r * ldc + c]       = v0;
            *(float2*)&C[(size_t)(r + 8) * ldc + c] = v1;
        }
    }
}

// -------------------- GRU gates + scatter --------------------
__global__ void k_gru_scatter(const float* __restrict__ memory,
                              const float* __restrict__ bih,
                              const float* __restrict__ bhh,
                              const float* __restrict__ times,
                              const int* __restrict__ src,
                              const int* __restrict__ dst,
                              float* __restrict__ out_mem,
                              float* __restrict__ out_lu) {
    int i = blockIdx.x;
    int e = i & (BB - 1);
    int node = (i < BB) ? src[e] : dst[e];
    if (g_lastpos[node] != i) return;      // only the last message per node writes
    const float* gi   = &g_Gi[(size_t)i * NP];
    const float* gh   = &g_Gh[(size_t)i * NP];
    const float* hrow = memory + (size_t)node * DM;   // exact fp32 h
    float* om = out_mem + (size_t)node * DM;
    for (int j = threadIdx.x; j < DM; j += blockDim.x) {
        float r = sigf(gi[j]        + bih[j]        + gh[j]        + bhh[j]);
        float z = sigf(gi[DM + j]   + bih[DM + j]   + gh[DM + j]   + bhh[DM + j]);
        float n = tanhf(gi[2*DM + j] + bih[2*DM + j] + r * (gh[2*DM + j] + bhh[2*DM + j]));
        float h = hrow[j];
        om[j] = (1.0f - z) * n + z * h;
    }
    if (threadIdx.x == 0) out_lu[node] = times[e];
}

// -------------------- score MLP tail (layers 2, 3) --------------------
__global__ void k_scores_tail(const float* __restrict__ b1,
                              const float* __restrict__ W2, const float* __restrict__ b2,
                              const float* __restrict__ W3, const float* __restrict__ b3,
                              float* __restrict__ out) {
    __shared__ float sW2[80 * 10];
    __shared__ float sW3[10];
    __shared__ float sb1[80];
    __shared__ float sb2[10];
    int tid = threadIdx.x;
    if (tid < 80) sb1[tid] = b1[tid];
    if (tid >= 128 && tid < 128 + 10) { sW3[tid - 128] = W3[tid - 128]; sb2[tid - 128] = b2[tid - 128]; }
    for (int j = tid; j < 800; j += blockDim.x) sW2[j] = W2[j];
    __syncthreads();

    int i = blockIdx.x * blockDim.x + tid;    // 0..8191
    const float* h1row = &g_H1[(size_t)i * NX];
    float h1[80];
    #pragma unroll 8
    for (int j = 0; j < 80; j++) h1[j] = fmaxf(h1row[j] + sb1[j], 0.0f);
    float sc = b3[0];
    #pragma unroll
    for (int c = 0; c < 10; c++) {
        float h2 = sb2[c];
        #pragma unroll 8
        for (int j = 0; j < 80; j++) h2 = fmaf(h1[j], sW2[j * 10 + c], h2);
        sc = fmaf(fmaxf(h2, 0.0f), sW3[c], sc);
    }
    out[i] = sc;    // rows 0..B-1 = score_pos, B..2B-1 = score_neg
}

// -------------------- launcher --------------------
extern "C" void kernel_launch(void* const* d_in, const int* in_sizes, int n_in,
                              void* d_out, int out_size) {
    const float* memory      = (const float*)d_in[0];
    const float* last_update = (const float*)d_in[1];
    const float* comm_emb    = (const float*)d_in[2];
    const float* ef_table    = (const float*)d_in[3];
    const float* edge_times  = (const float*)d_in[4];
    const float* time_w      = (const float*)d_in[5];
    const float* time_b      = (const float*)d_in[6];
    const float* W_ih        = (const float*)d_in[7];
    const float* W_hh        = (const float*)d_in[8];
    const float* b_ih        = (const float*)d_in[9];
    const float* b_hh        = (const float*)d_in[10];
    const float* W1          = (const float*)d_in[11];
    const float* b1          = (const float*)d_in[12];
    const float* W2          = (const float*)d_in[13];
    const float* b2          = (const float*)d_in[14];
    const float* W3          = (const float*)d_in[15];
    const float* b3          = (const float*)d_in[16];
    const int*   src         = (const int*)d_in[17];
    const int*   dst         = (const int*)d_in[18];
    const int*   neg         = (const int*)d_in[19];
    const int*   edge_idxs   = (const int*)d_in[20];

    float* out      = (float*)d_out;
    float* out_sc   = out;                                   // score_pos[B], score_neg[B]
    float* out_mem  = out + 2 * BB;                          // new_memory [N*DM]
    float* out_lu   = out + 2 * BB + (size_t)NN * DM;        // new_last_update [N]

    // 1) copy memory -> out_mem
    {
        int n4 = (NN * DM) / 4;
        k_copy4<<<(n4 + 255) / 256, 256>>>((const float4*)memory, (float4*)out_mem, n4);
    }
    // 2) copy last_update -> out_lu
    {
        int n4 = NN / 4;
        k_copy4<<<(n4 + 255) / 256, 256>>>((const float4*)last_update, (float4*)out_lu, n4);
    }
    // 3) pad/split weights
    {
        int total = NP * KP1 + NP * KP2;
        k_pad_w<<<(total + 255) / 256, 256>>>(W_ih, W_hh);
        k_pad_w1<<<(NX * KX + 255) / 256, 256>>>(W1);
    }
    // 4) build message matrix + score input matrix (fp16)
    k_build_msgs<<<ROWS, 256>>>(memory, last_update, ef_table, edge_times,
                                time_w, time_b, src, dst, edge_idxs);
    k_build_X<<<ROWS, 256>>>(memory, comm_emb, src, dst, neg);
    // 5) last-message aggregation
    k_lp_init<<<(2 * BB + 255) / 256, 256>>>(src, dst);
    k_lp_max <<<(2 * BB + 255) / 256, 256>>>(src, dst);
    // 6) split-fp16 tensor-core GEMMs (operands bound in device code)
    {
        dim3 g1(NP / 64, ROWS / 128);      // (24, 64)
        k_mma<0><<<g1, 256>>>();
        k_mma<1><<<g1, 256>>>();
        dim3 g2(NX / 64, ROWS / 128);      // (2, 64)
        k_mma<2><<<g2, 256>>>();
    }
    // 7) score MLP tail
    k_scores_tail<<<ROWS / 256, 256>>>(b1, W2, b2, W3, b3, out_sc);
    // 8) gates + scatter
    k_gru_scatter<<<ROWS, 512>>>(memory, b_ih, b_hh, edge_times, src, dst, out_mem, out_lu);
}

// round 11
// speedup vs baseline: 4.4210x; 1.3577x over previous
#include <cuda_runtime.h>
#include <cuda_fp16.h>
#include <cstdint>

// Problem constants
#define NN   200000
#define DM   500
#define BB   4096
#define MSG  1501        // 2*DM + 1 + DM
#define G3   1500        // 3*DM
#define ROWS 8192        // 2*B message rows

// Padded dims for guard-free GEMMs
#define KP1  1504        // msgs K padded (1501 -> 1504, mult of 32)
#define KP2  512         // h K padded (500 -> 512) == N of the gh_n GEMM
#define NP   1536        // fused GRU GEMM N padded (1500 -> 1536)
#define KX   2048        // score layer-1 K padded (4 segments of 512)
#define NX   128         // score layer-1 N padded (80 -> 128)

typedef __half fp16;

// -------------------- scratch (device globals, no allocation) --------------------
// ONLY referenced from device code (host-side symbol name = host shadow addr,
// silently dereferenced via ATS on GB300 — round 2-4 bug).
__device__ __align__(128) fp16 g_A1  [(size_t)ROWS * KP1];   // msgs, fp16
__device__ __align__(128) fp16 g_Wc  [(size_t)NP   * KP1];   // W_ih + fused W_hh(r,z)
__device__ __align__(128) fp16 g_Whn [(size_t)KP2  * KP2];   // W_hh n-gate rows, padded
__device__ __align__(128) fp16 g_Xp  [(size_t)ROWS * KX ];
__device__ __align__(128) fp16 g_W1ph[(size_t)NX   * KX ];
__device__ __align__(128) fp16 g_W1pl[(size_t)NX   * KX ];
__device__ __align__(128) float g_Gc [(size_t)ROWS * NP ];   // msgs @ Wc^T
__device__ __align__(128) float g_Ghn[(size_t)ROWS * KP2];   // h @ Whn^T
__device__ __align__(128) float g_H1 [(size_t)ROWS * NX ];
__device__ int g_lastpos[NN];

// -------------------- helpers --------------------
__device__ __forceinline__ float sigf(float x) { return 1.0f / (1.0f + expf(-x)); }
__device__ __forceinline__ void split_fp16(float x, fp16* ph, fp16* pl) {
    fp16 h = __float2half_rn(x);
    fp16 l = __float2half_rn(x - __half2float(h));
    *ph = h; *pl = l;
}

// -------------------- copy kernel --------------------
__global__ void k_copy4(const float4* __restrict__ src, float4* __restrict__ dst, int n4) {
    int i = blockIdx.x * blockDim.x + threadIdx.x;
    if (i < n4) dst[i] = src[i];
}

// -------------------- weight prep --------------------
// Wc[n,k] = W_ih[n,k] + (n<2*DM && k<DM ? W_hh[n,k] : 0), zero-padded to NP x KP1.
// Whn[n,k] = W_hh[2*DM+n, k] (n<DM, k<DM), zero-padded to KP2 x KP2.
__global__ void k_pad_w(const float* __restrict__ Wih, const float* __restrict__ Whh) {
    const int total1 = NP * KP1;
    const int total2 = KP2 * KP2;
    int idx = blockIdx.x * blockDim.x + threadIdx.x;
    if (idx < total1) {
        int r = idx / KP1, k = idx - r * KP1;
        float v = 0.0f;
        if (r < G3 && k < MSG) v = Wih[r * MSG + k];
        if (r < 2 * DM && k < DM) v += Whh[r * DM + k];
        g_Wc[idx] = __float2half_rn(v);
    } else if (idx < total1 + total2) {
        int j = idx - total1;
        int n = j >> 9, k = j & (KP2 - 1);
        float v = (n < DM && k < DM) ? Whh[(2 * DM + n) * DM + k] : 0.0f;
        g_Whn[j] = __float2half_rn(v);
    }
}

__global__ void k_pad_w1(const float* __restrict__ W1) {
    int idx = blockIdx.x * blockDim.x + threadIdx.x;   // NX * KX
    if (idx >= NX * KX) return;
    int n = idx >> 11, k = idx & (KX - 1);
    int seg = k >> 9, j = k & 511;
    float v = 0.0f;
    if (n < 80 && j < DM) v = W1[(seg * DM + j) * 80 + n];
    split_fp16(v, &g_W1ph[idx], &g_W1pl[idx]);
}

// -------------------- build message matrix (fp16) --------------------
__global__ void k_build_msgs(const float* __restrict__ memory,
                             const float* __restrict__ last_update,
                             const float* __restrict__ ef_table,
                             const float* __restrict__ times,
                             const float* __restrict__ time_w,
                             const float* __restrict__ time_b,
                             const int* __restrict__ src,
                             const int* __restrict__ dst,
                             const int* __restrict__ edge_idxs) {
    int i = blockIdx.x;                 // 0..8191
    int e = i & (BB - 1);
    bool srow = (i < BB);
    int a = srow ? src[e] : dst[e];     // node owning this message
    int b = srow ? dst[e] : src[e];
    float t  = times[e];
    float dt = t - last_update[a];
    size_t ro = (size_t)i * KP1;
    const float* ma = memory + (size_t)a * DM;
    const float* mb = memory + (size_t)b * DM;
    for (int j = threadIdx.x; j < DM; j += blockDim.x) {
        g_A1[ro + j]          = __float2half_rn(ma[j]);
        g_A1[ro + DM + j]     = __float2half_rn(mb[j]);
        float enc = cosf(fmaf(dt, time_w[j], time_b[j]));
        g_A1[ro + 2*DM+1 + j] = __float2half_rn(enc);
    }
    if (threadIdx.x == 0) {
        g_A1[ro + 2*DM] = __float2half_rn(ef_table[edge_idxs[e]]);
        for (int p = MSG; p < KP1; p++) g_A1[ro + p] = __float2half_rn(0.f);
    }
}

// -------------------- build score-MLP input matrix --------------------
__global__ void k_build_X(const float* __restrict__ memory,
                          const float* __restrict__ ce,
                          const int* __restrict__ src,
                          const int* __restrict__ dst,
                          const int* __restrict__ neg) {
    int i = blockIdx.x;                 // 0..8191
    int e = i & (BB - 1);
    int s = src[e];
    int o = (i < BB) ? dst[e] : neg[e];
    size_t ro = (size_t)i * KX;
    const float* seg0 = memory + (size_t)s * DM;
    const float* seg1 = ce     + (size_t)s * DM;
    const float* seg2 = memory + (size_t)o * DM;
    const float* seg3 = ce     + (size_t)o * DM;
    for (int k = threadIdx.x; k < KX; k += blockDim.x) {
        int seg = k >> 9, j = k & 511;
        float v = 0.0f;
        if (j < DM) {
            const float* p = (seg == 0) ? seg0 : (seg == 1) ? seg1 : (seg == 2) ? seg2 : seg3;
            v = p[j];
        }
        g_Xp[ro + k] = __float2half_rn(v);
    }
}

// -------------------- last-message aggregation --------------------
__global__ void k_lp_init(const int* __restrict__ src, const int* __restrict__ dst) {
    int i = blockIdx.x * blockDim.x + threadIdx.x;
    if (i >= 2 * BB) return;
    int node = (i < BB) ? src[i] : dst[i - BB];
    g_lastpos[node] = -1;
}
__global__ void k_lp_max(const int* __restrict__ src, const int* __restrict__ dst) {
    int i = blockIdx.x * blockDim.x + threadIdx.x;
    if (i >= 2 * BB) return;
    int node = (i < BB) ? src[i] : dst[i - BB];
    atomicMax(&g_lastpos[node], i);
}

// -------------------- fp16 tensor-core GEMM: C = A @ B^T --------------------
// MODE 0: g_Gc  = g_A1 @ g_Wc^T          (K=1504, N=1536, single product)
// MODE 1: g_Ghn = g_A1[:, :512] @ g_Whn^T (K=512,  N=512,  single product)
// MODE 2: g_H1  = g_Xp @ (g_W1ph+g_W1pl)^T (K=2048, N=128, split 2-product)
// BM=128, BN=64, BK=32, 256 threads, double-buffered cp.async, mma.m16n8k16.f16.
#define SSTW 20                  // smem row stride in words (16 data + 4 pad)

#define MMA_FP16(ACC, A_, B_) \
    asm volatile("mma.sync.aligned.m16n8k16.row.col.f32.f16.f16.f32 " \
        "{%0,%1,%2,%3}, {%4,%5,%6,%7}, {%8,%9}, {%0,%1,%2,%3};" \
        : "+f"((ACC)[0]), "+f"((ACC)[1]), "+f"((ACC)[2]), "+f"((ACC)[3]) \
        : "r"((A_)[0]), "r"((A_)[1]), "r"((A_)[2]), "r"((A_)[3]), \
          "r"((B_)[0]), "r"((B_)[1]))

template <int MODE>
__global__ void __launch_bounds__(256) k_mma() {
    constexpr bool SPLIT = (MODE == 2);
    const fp16* __restrict__ A  = (MODE == 2) ? g_Xp : g_A1;
    const int lda               = (MODE == 2) ? KX : KP1;
    const fp16* __restrict__ Bh = (MODE == 0) ? g_Wc : (MODE == 1) ? g_Whn : g_W1ph;
    const fp16* __restrict__ Bl = g_W1pl;                       // used only when SPLIT
    const int ldb               = (MODE == 0) ? KP1 : (MODE == 1) ? KP2 : KX;
    float* __restrict__ C       = (MODE == 0) ? g_Gc : (MODE == 1) ? g_Ghn : g_H1;
    const int ldc               = (MODE == 0) ? NP : (MODE == 1) ? KP2 : NX;
    const int K                 = ldb;   // B is [N x K] with row stride == K

    __shared__ __align__(16) uint32_t smA [2][128 * SSTW];            // 20 KB
    __shared__ __align__(16) uint32_t smBh[2][ 64 * SSTW];            // 10 KB
    __shared__ __align__(16) uint32_t smBl[SPLIT ? 2 : 1][64 * SSTW]; // 10/5 KB

    const int tid  = threadIdx.x;
    const int lane = tid & 31;
    const int wid  = tid >> 5;          // 0..7
    const int wm   = wid >> 1;          // 0..3 -> 32-row slice of 128
    const int wn   = wid & 1;           // 0..1 -> 32-col slice of 64
    const int q    = lane >> 2;         // 0..7
    const int rr   = lane & 3;          // 0..3

    const int row0 = blockIdx.y * 128;
    const int col0 = blockIdx.x * 64;

    float acc[2][4][4];
    #pragma unroll
    for (int am = 0; am < 2; am++)
        #pragma unroll
        for (int bn = 0; bn < 4; bn++)
            #pragma unroll
            for (int c = 0; c < 4; c++) acc[am][bn][c] = 0.0f;

    const int K_tiles = K >> 5;

    auto load_stage = [&](int stage, int k0) {
        // A tile: 128 rows x 32 fp16 = 512 x 16B chunks; 256 thr -> 2 each
        #pragma unroll
        for (int i = 0; i < 2; i++) {
            int f  = i * 256 + tid;      // 0..511
            int r  = f >> 2;             // 0..127
            int w4 = (f & 3) * 4;        // word offset 0,4,8,12
            const fp16* gp = A + (size_t)(row0 + r) * lda + k0 + w4 * 2;
            uint32_t sp = (uint32_t)__cvta_generic_to_shared(&smA[stage][r * SSTW + w4]);
            asm volatile("cp.async.cg.shared.global [%0], [%1], 16;" :: "r"(sp), "l"(gp));
        }
        // B tiles: 64 rows x 32 fp16 = 256 chunks each
        {
            int r  = tid >> 2;           // 0..63
            int w4 = (tid & 3) * 4;
            int eo = k0 + w4 * 2;
            const fp16* gph = Bh + (size_t)(col0 + r) * ldb + eo;
            uint32_t sph = (uint32_t)__cvta_generic_to_shared(&smBh[stage][r * SSTW + w4]);
            asm volatile("cp.async.cg.shared.global [%0], [%1], 16;" :: "r"(sph), "l"(gph));
            if constexpr (SPLIT) {
                const fp16* gpl = Bl + (size_t)(col0 + r) * ldb + eo;
                uint32_t spl = (uint32_t)__cvta_generic_to_shared(&smBl[stage][r * SSTW + w4]);
                asm volatile("cp.async.cg.shared.global [%0], [%1], 16;" :: "r"(spl), "l"(gpl));
            }
        }
        asm volatile("cp.async.commit_group;");
    };

    load_stage(0, 0);

    for (int t = 0; t < K_tiles; t++) {
        int s = t & 1;
        if (t + 1 < K_tiles) {
            load_stage((t + 1) & 1, (t + 1) << 5);
            asm volatile("cp.async.wait_group 1;");
        } else {
            asm volatile("cp.async.wait_group 0;");
        }
        __syncthreads();

        const uint32_t* As  = smA [s];
        const uint32_t* Bsh = smBh[s];
        const uint32_t* Bsl = smBl[SPLIT ? s : 0];

        #pragma unroll
        for (int kk = 0; kk < 2; kk++) {            // two k16 steps per 32-elem tile
            int kw = kk * 8 + rr;                   // word index within row
            uint32_t a[2][4], bh[4][2], bl[4][2];
            #pragma unroll
            for (int am = 0; am < 2; am++) {
                int base = (wm * 32 + am * 16 + q) * SSTW + kw;
                a[am][0] = As[base];
                a[am][1] = As[base + 8 * SSTW];
                a[am][2] = As[base + 4];
                a[am][3] = As[base + 8 * SSTW + 4];
            }
            #pragma unroll
            for (int bn = 0; bn < 4; bn++) {
                int base = (wn * 32 + bn * 8 + q) * SSTW + kw;
                bh[bn][0] = Bsh[base];
                bh[bn][1] = Bsh[base + 4];
                if constexpr (SPLIT) {
                    bl[bn][0] = Bsl[base];
                    bl[bn][1] = Bsl[base + 4];
                }
            }
            #pragma unroll
            for (int am = 0; am < 2; am++)
                #pragma unroll
                for (int bn = 0; bn < 4; bn++) {
                    MMA_FP16(acc[am][bn], a[am], bh[bn]);
                    if constexpr (SPLIT) MMA_FP16(acc[am][bn], a[am], bl[bn]);
                }
        }
        __syncthreads();
    }

    // epilogue
    #pragma unroll
    for (int am = 0; am < 2; am++) {
        int r = row0 + wm * 32 + am * 16 + q;
        #pragma unroll
        for (int bn = 0; bn < 4; bn++) {
            int c = col0 + wn * 32 + bn * 8 + rr * 2;
            float2 v0 = {acc[am][bn][0], acc[am][bn][1]};
            float2 v1 = {acc[am][bn][2], acc[am][bn][3]};
            *(float2*)&C[(size_t)r * ldc + c]       = v0;
            *(float2*)&C[(size_t)(r + 8) * ldc + c] = v1;
        }
    }
}

// -------------------- GRU gates + scatter --------------------
// g_Gc row: [0:500)=r preact (gi+gh), [500:1000)=z preact, [1000:1500)=gi_n.
// g_Ghn row: [0:500)=gh_n.
__global__ void k_gru_scatter(const float* __restrict__ memory,
                              const float* __restrict__ bih,
                              const float* __restrict__ bhh,
                              const float* __restrict__ times,
                              const int* __restrict__ src,
                              const int* __restrict__ dst,
                              float* __restrict__ out_mem,
                              float* __restrict__ out_lu) {
    int i = blockIdx.x;
    int e = i & (BB - 1);
    int node = (i < BB) ? src[e] : dst[e];
    if (g_lastpos[node] != i) return;      // only the last message per node writes
    const float* gc   = &g_Gc [(size_t)i * NP];
    const float* ghn  = &g_Ghn[(size_t)i * KP2];
    const float* hrow = memory + (size_t)node * DM;   // exact fp32 h
    float* om = out_mem + (size_t)node * DM;
    for (int j = threadIdx.x; j < DM; j += blockDim.x) {
        float r = sigf(gc[j]      + bih[j]      + bhh[j]);
        float z = sigf(gc[DM + j] + bih[DM + j] + bhh[DM + j]);
        float n = tanhf(gc[2*DM + j] + bih[2*DM + j] + r * (ghn[j] + bhh[2*DM + j]));
        float h = hrow[j];
        om[j] = (1.0f - z) * n + z * h;
    }
    if (threadIdx.x == 0) out_lu[node] = times[e];
}

// -------------------- score MLP tail (layers 2, 3) --------------------
__global__ void k_scores_tail(const float* __restrict__ b1,
                              const float* __restrict__ W2, const float* __restrict__ b2,
                              const float* __restrict__ W3, const float* __restrict__ b3,
                              float* __restrict__ out) {
    __shared__ float sW2[80 * 10];
    __shared__ float sW3[10];
    __shared__ float sb1[80];
    __shared__ float sb2[10];
    int tid = threadIdx.x;
    if (tid < 80) sb1[tid] = b1[tid];
    if (tid >= 128 && tid < 128 + 10) { sW3[tid - 128] = W3[tid - 128]; sb2[tid - 128] = b2[tid - 128]; }
    for (int j = tid; j < 800; j += blockDim.x) sW2[j] = W2[j];
    __syncthreads();

    int i = blockIdx.x * blockDim.x + tid;    // 0..8191
    const float* h1row = &g_H1[(size_t)i * NX];
    float h1[80];
    #pragma unroll 8
    for (int j = 0; j < 80; j++) h1[j] = fmaxf(h1row[j] + sb1[j], 0.0f);
    float sc = b3[0];
    #pragma unroll
    for (int c = 0; c < 10; c++) {
        float h2 = sb2[c];
        #pragma unroll 8
        for (int j = 0; j < 80; j++) h2 = fmaf(h1[j], sW2[j * 10 + c], h2);
        sc = fmaf(fmaxf(h2, 0.0f), sW3[c], sc);
    }
    out[i] = sc;    // rows 0..B-1 = score_pos, B..2B-1 = score_neg
}

// -------------------- launcher --------------------
extern "C" void kernel_launch(void* const* d_in, const int* in_sizes, int n_in,
                              void* d_out, int out_size) {
    const float* memory      = (const float*)d_in[0];
    const float* last_update = (const float*)d_in[1];
    const float* comm_emb    = (const float*)d_in[2];
    const float* ef_table    = (const float*)d_in[3];
    const float* edge_times  = (const float*)d_in[4];
    const float* time_w      = (const float*)d_in[5];
    const float* time_b      = (const float*)d_in[6];
    const float* W_ih        = (const float*)d_in[7];
    const float* W_hh        = (const float*)d_in[8];
    const float* b_ih        = (const float*)d_in[9];
    const float* b_hh        = (const float*)d_in[10];
    const float* W1          = (const float*)d_in[11];
    const float* b1          = (const float*)d_in[12];
    const float* W2          = (const float*)d_in[13];
    const float* b2          = (const float*)d_in[14];
    const float* W3          = (const float*)d_in[15];
    const float* b3          = (const float*)d_in[16];
    const int*   src         = (const int*)d_in[17];
    const int*   dst         = (const int*)d_in[18];
    const int*   neg         = (const int*)d_in[19];
    const int*   edge_idxs   = (const int*)d_in[20];

    float* out      = (float*)d_out;
    float* out_sc   = out;                                   // score_pos[B], score_neg[B]
    float* out_mem  = out + 2 * BB;                          // new_memory [N*DM]
    float* out_lu   = out + 2 * BB + (size_t)NN * DM;        // new_last_update [N]

    // 1) copy memory -> out_mem
    {
        int n4 = (NN * DM) / 4;
        k_copy4<<<(n4 + 255) / 256, 256>>>((const float4*)memory, (float4*)out_mem, n4);
    }
    // 2) copy last_update -> out_lu
    {
        int n4 = NN / 4;
        k_copy4<<<(n4 + 255) / 256, 256>>>((const float4*)last_update, (float4*)out_lu, n4);
    }
    // 3) pad/fuse weights
    {
        int total = NP * KP1 + KP2 * KP2;
        k_pad_w<<<(total + 255) / 256, 256>>>(W_ih, W_hh);
        k_pad_w1<<<(NX * KX + 255) / 256, 256>>>(W1);
    }
    // 4) build message matrix + score input matrix (fp16)
    k_build_msgs<<<ROWS, 256>>>(memory, last_update, ef_table, edge_times,
                                time_w, time_b, src, dst, edge_idxs);
    k_build_X<<<ROWS, 256>>>(memory, comm_emb, src, dst, neg);
    // 5) last-message aggregation
    k_lp_init<<<(2 * BB + 255) / 256, 256>>>(src, dst);
    k_lp_max <<<(2 * BB + 255) / 256, 256>>>(src, dst);
    // 6) tensor-core GEMMs (operands bound in device code)
    {
        dim3 g0(NP / 64, ROWS / 128);      // (24, 64) fused Wc GEMM
        k_mma<0><<<g0, 256>>>();
        dim3 g1(KP2 / 64, ROWS / 128);     // (8, 64)  gh_n GEMM
        k_mma<1><<<g1, 256>>>();
        dim3 g2(NX / 64, ROWS / 128);      // (2, 64)  score layer-1
        k_mma<2><<<g2, 256>>>();
    }
    // 7) score MLP tail
    k_scores_tail<<<ROWS / 256, 256>>>(b1, W2, b2, W3, b3, out_sc);
    // 8) gates + scatter
    k_gru_scatter<<<ROWS, 512>>>(memory, b_ih, b_hh, edge_times, src, dst, out_mem, out_lu);
}

// round 12
// speedup vs baseline: 4.5862x; 1.0374x over previous
#include <cuda_runtime.h>
#include <cuda_fp16.h>
#include <cstdint>

// Problem constants
#define NN   200000
#define DM   500
#define BB   4096
#define MSG  1501        // 2*DM + 1 + DM
#define G3   1500        // 3*DM
#define ROWS 8192        // 2*B message rows

// Padded dims for guard-free GEMMs
#define KP1  1504        // msgs K padded (1501 -> 1504, mult of 32)
#define KP2  512         // h K padded (500 -> 512) == N of the gh_n GEMM
#define NP   1536        // fused GRU GEMM N padded (1500 -> 1536)
#define KX   2048        // score layer-1 K padded (4 segments of 512)
#define NX   128         // score layer-1 N padded (80 -> 128)

typedef __half fp16;

// -------------------- scratch (device globals, no allocation) --------------------
// ONLY referenced from device code (host-side symbol name = host shadow addr,
// silently dereferenced via ATS on GB300 — round 2-4 bug).
__device__ __align__(128) fp16 g_A1  [(size_t)ROWS * KP1];   // msgs, fp16
__device__ __align__(128) fp16 g_Wc  [(size_t)NP   * KP1];   // W_ih + fused W_hh(r,z)
__device__ __align__(128) fp16 g_Whn [(size_t)KP2  * KP2];   // W_hh n-gate rows, padded
__device__ __align__(128) fp16 g_Xp  [(size_t)ROWS * KX ];
__device__ __align__(128) fp16 g_W1ph[(size_t)NX   * KX ];
__device__ __align__(128) fp16 g_W1pl[(size_t)NX   * KX ];
__device__ __align__(128) float g_Gc [(size_t)ROWS * NP ];   // msgs @ Wc^T
__device__ __align__(128) float g_Ghn[(size_t)ROWS * KP2];   // h @ Whn^T
__device__ __align__(128) float g_H1 [(size_t)ROWS * NX ];
__device__ int g_lastpos[NN];

// -------------------- helpers --------------------
__device__ __forceinline__ float sigf(float x) { return 1.0f / (1.0f + expf(-x)); }
__device__ __forceinline__ void split_fp16(float x, fp16* ph, fp16* pl) {
    fp16 h = __float2half_rn(x);
    fp16 l = __float2half_rn(x - __half2float(h));
    *ph = h; *pl = l;
}

// -------------------- copy kernel --------------------
__global__ void k_copy4(const float4* __restrict__ src, float4* __restrict__ dst, int n4) {
    int i = blockIdx.x * blockDim.x + threadIdx.x;
    if (i < n4) dst[i] = src[i];
}

// -------------------- weight prep (Wc, Whn, W1 split) — one kernel --------------------
__global__ void k_pad_all(const float* __restrict__ Wih, const float* __restrict__ Whh,
                          const float* __restrict__ W1) {
    const int total1 = NP * KP1;
    const int total2 = KP2 * KP2;
    const int total3 = NX * KX;
    int idx = blockIdx.x * blockDim.x + threadIdx.x;
    if (idx < total1) {
        int r = idx / KP1, k = idx - r * KP1;
        float v = 0.0f;
        if (r < G3 && k < MSG) v = Wih[r * MSG + k];
        if (r < 2 * DM && k < DM) v += Whh[r * DM + k];
        g_Wc[idx] = __float2half_rn(v);
    } else if (idx < total1 + total2) {
        int j = idx - total1;
        int n = j >> 9, k = j & (KP2 - 1);
        float v = (n < DM && k < DM) ? Whh[(2 * DM + n) * DM + k] : 0.0f;
        g_Whn[j] = __float2half_rn(v);
    } else if (idx < total1 + total2 + total3) {
        int j = idx - total1 - total2;
        int n = j >> 11, k = j & (KX - 1);
        int seg = k >> 9, kk = k & 511;
        float v = 0.0f;
        if (n < 80 && kk < DM) v = W1[(seg * DM + kk) * 80 + n];
        split_fp16(v, &g_W1ph[j], &g_W1pl[j]);
    }
}

// -------------------- build message + score-input matrices — one kernel --------------------
__global__ void k_build(const float* __restrict__ memory,
                        const float* __restrict__ last_update,
                        const float* __restrict__ ef_table,
                        const float* __restrict__ times,
                        const float* __restrict__ time_w,
                        const float* __restrict__ time_b,
                        const float* __restrict__ ce,
                        const int* __restrict__ src,
                        const int* __restrict__ dst,
                        const int* __restrict__ neg,
                        const int* __restrict__ edge_idxs) {
    int blk = blockIdx.x;
    if (blk < ROWS) {
        // ---- message row ----
        int i = blk;
        int e = i & (BB - 1);
        bool srow = (i < BB);
        int a = srow ? src[e] : dst[e];
        int b = srow ? dst[e] : src[e];
        float t  = times[e];
        float dt = t - last_update[a];
        size_t ro = (size_t)i * KP1;
        const float* ma = memory + (size_t)a * DM;
        const float* mb = memory + (size_t)b * DM;
        for (int j = threadIdx.x; j < DM; j += blockDim.x) {
            g_A1[ro + j]          = __float2half_rn(ma[j]);
            g_A1[ro + DM + j]     = __float2half_rn(mb[j]);
            float enc = cosf(fmaf(dt, time_w[j], time_b[j]));
            g_A1[ro + 2*DM+1 + j] = __float2half_rn(enc);
        }
        if (threadIdx.x == 0) {
            g_A1[ro + 2*DM] = __float2half_rn(ef_table[edge_idxs[e]]);
            for (int p = MSG; p < KP1; p++) g_A1[ro + p] = __float2half_rn(0.f);
        }
    } else {
        // ---- score MLP input row ----
        int i = blk - ROWS;
        int e = i & (BB - 1);
        int s = src[e];
        int o = (i < BB) ? dst[e] : neg[e];
        size_t ro = (size_t)i * KX;
        const float* seg0 = memory + (size_t)s * DM;
        const float* seg1 = ce     + (size_t)s * DM;
        const float* seg2 = memory + (size_t)o * DM;
        const float* seg3 = ce     + (size_t)o * DM;
        for (int k = threadIdx.x; k < KX; k += blockDim.x) {
            int seg = k >> 9, j = k & 511;
            float v = 0.0f;
            if (j < DM) {
                const float* p = (seg == 0) ? seg0 : (seg == 1) ? seg1 : (seg == 2) ? seg2 : seg3;
                v = p[j];
            }
            g_Xp[ro + k] = __float2half_rn(v);
        }
    }
}

// -------------------- last-message aggregation --------------------
__global__ void k_lp_init(const int* __restrict__ src, const int* __restrict__ dst) {
    int i = blockIdx.x * blockDim.x + threadIdx.x;
    if (i >= 2 * BB) return;
    int node = (i < BB) ? src[i] : dst[i - BB];
    g_lastpos[node] = -1;
}
__global__ void k_lp_max(const int* __restrict__ src, const int* __restrict__ dst) {
    int i = blockIdx.x * blockDim.x + threadIdx.x;
    if (i >= 2 * BB) return;
    int node = (i < BB) ? src[i] : dst[i - BB];
    atomicMax(&g_lastpos[node], i);
}

// -------------------- fp16 tensor-core GEMM: C = A @ B^T --------------------
// MODE 0: g_Gc  = g_A1 @ g_Wc^T            (K=1504, N=1536, single product, 3-stage)
// MODE 1: g_Ghn = g_A1[:, :512] @ g_Whn^T  (K=512,  N=512,  single product, 3-stage)
// MODE 2: g_H1  = g_Xp @ (g_W1ph+g_W1pl)^T (K=2048, N=128,  split 2-product, 2-stage)
// BM=128, BN=64, BK=32, 256 threads, cp.async pipeline, ldmatrix.x4 + mma.m16n8k16.f16.
#define SSTW 20                  // smem row stride in words (16 data + 4 pad)

#define MMA_FP16(ACC, A_, B0, B1) \
    asm volatile("mma.sync.aligned.m16n8k16.row.col.f32.f16.f16.f32 " \
        "{%0,%1,%2,%3}, {%4,%5,%6,%7}, {%8,%9}, {%0,%1,%2,%3};" \
        : "+f"((ACC)[0]), "+f"((ACC)[1]), "+f"((ACC)[2]), "+f"((ACC)[3]) \
        : "r"((A_)[0]), "r"((A_)[1]), "r"((A_)[2]), "r"((A_)[3]), \
          "r"(B0), "r"(B1))

#define LDSM_X4(R, ADDR) \
    asm volatile("ldmatrix.sync.aligned.m8n8.x4.shared.b16 {%0,%1,%2,%3}, [%4];" \
        : "=r"((R)[0]), "=r"((R)[1]), "=r"((R)[2]), "=r"((R)[3]) : "r"(ADDR))

template <int MODE>
__global__ void __launch_bounds__(256) k_mma() {
    constexpr bool SPLIT = (MODE == 2);
    constexpr int  ST    = SPLIT ? 2 : 3;    // pipeline stages (smem budget)
    const fp16* __restrict__ A  = (MODE == 2) ? g_Xp : g_A1;
    const int lda               = (MODE == 2) ? KX : KP1;
    const fp16* __restrict__ Bh = (MODE == 0) ? g_Wc : (MODE == 1) ? g_Whn : g_W1ph;
    const fp16* __restrict__ Bl = g_W1pl;                       // used only when SPLIT
    const int ldb               = (MODE == 0) ? KP1 : (MODE == 1) ? KP2 : KX;
    float* __restrict__ C       = (MODE == 0) ? g_Gc : (MODE == 1) ? g_Ghn : g_H1;
    const int ldc               = (MODE == 0) ? NP : (MODE == 1) ? KP2 : NX;
    const int K                 = ldb;   // B is [N x K] with row stride == K

    __shared__ __align__(16) uint32_t smA [ST][128 * SSTW];                 // 10 KB/stage
    __shared__ __align__(16) uint32_t smBh[ST][ 64 * SSTW];                 // 5 KB/stage
    __shared__ __align__(16) uint32_t smBl[SPLIT ? ST : 1][SPLIT ? 64 * SSTW : 4];

    const int tid  = threadIdx.x;
    const int lane = tid & 31;
    const int wid  = tid >> 5;          // 0..7
    const int wm   = wid >> 1;          // 0..3 -> 32-row slice of 128
    const int wn   = wid & 1;           // 0..1 -> 32-col slice of 64
    const int q    = lane >> 2;         // 0..7
    const int rr   = lane & 3;          // 0..3

    const int row0 = blockIdx.y * 128;
    const int col0 = blockIdx.x * 64;

    // ldmatrix per-lane source mapping
    const int rowA0 = wm * 32 + (lane & 15);                    // + am*16
    const int kwA   = (lane >> 4) << 2;                         // + kk*8
    const int rowB0 = wn * 32 + ((lane >> 4) << 3) + (lane & 7);// + p*16
    const int kwB   = ((lane >> 3) & 1) << 2;                   // + kk*8

    float acc[2][4][4];
    #pragma unroll
    for (int am = 0; am < 2; am++)
        #pragma unroll
        for (int bn = 0; bn < 4; bn++)
            #pragma unroll
            for (int c = 0; c < 4; c++) acc[am][bn][c] = 0.0f;

    const int K_tiles = K >> 5;

    auto load_stage = [&](int stage, int k0) {
        // A tile: 128 rows x 32 fp16 = 512 x 16B chunks; 256 thr -> 2 each
        #pragma unroll
        for (int i = 0; i < 2; i++) {
            int f  = i * 256 + tid;      // 0..511
            int r  = f >> 2;             // 0..127
            int w4 = (f & 3) * 4;        // word offset 0,4,8,12
            const fp16* gp = A + (size_t)(row0 + r) * lda + k0 + w4 * 2;
            uint32_t sp = (uint32_t)__cvta_generic_to_shared(&smA[stage][r * SSTW + w4]);
            asm volatile("cp.async.cg.shared.global [%0], [%1], 16;" :: "r"(sp), "l"(gp));
        }
        // B tiles: 64 rows x 32 fp16 = 256 chunks each
        {
            int r  = tid >> 2;           // 0..63
            int w4 = (tid & 3) * 4;
            int eo = k0 + w4 * 2;
            const fp16* gph = Bh + (size_t)(col0 + r) * ldb + eo;
            uint32_t sph = (uint32_t)__cvta_generic_to_shared(&smBh[stage][r * SSTW + w4]);
            asm volatile("cp.async.cg.shared.global [%0], [%1], 16;" :: "r"(sph), "l"(gph));
            if constexpr (SPLIT) {
                const fp16* gpl = Bl + (size_t)(col0 + r) * ldb + eo;
                uint32_t spl = (uint32_t)__cvta_generic_to_shared(&smBl[stage][r * SSTW + w4]);
                asm volatile("cp.async.cg.shared.global [%0], [%1], 16;" :: "r"(spl), "l"(gpl));
            }
        }
        asm volatile("cp.async.commit_group;");
    };

    // prologue: ST-1 stage loads (empty commit when out of range)
    #pragma unroll
    for (int p = 0; p < ST - 1; p++) {
        if (p < K_tiles) load_stage(p, p << 5);
        else             asm volatile("cp.async.commit_group;");
    }

    for (int t = 0; t < K_tiles; t++) {
        // prefetch stage t+ST-1 (buffer consumed at iter t-1, fenced by trailing sync)
        if (t + ST - 1 < K_tiles) load_stage((t + ST - 1) % ST, (t + ST - 1) << 5);
        else                      asm volatile("cp.async.commit_group;");
        // wait until stage t's group retired (<= ST-1 pending)
        if constexpr (ST == 3) asm volatile("cp.async.wait_group 2;");
        else                   asm volatile("cp.async.wait_group 1;");
        __syncthreads();

        const int s = t % ST;

        #pragma unroll
        for (int kk = 0; kk < 2; kk++) {            // two k16 steps per 32-elem tile
            uint32_t a[2][4], bh[2][4], bl[2][4];
            #pragma unroll
            for (int am = 0; am < 2; am++) {
                uint32_t ad = (uint32_t)__cvta_generic_to_shared(
                    &smA[s][(rowA0 + am * 16) * SSTW + kk * 8 + kwA]);
                LDSM_X4(a[am], ad);
            }
            #pragma unroll
            for (int p = 0; p < 2; p++) {
                uint32_t ad = (uint32_t)__cvta_generic_to_shared(
                    &smBh[s][(rowB0 + p * 16) * SSTW + kk * 8 + kwB]);
                LDSM_X4(bh[p], ad);
                if constexpr (SPLIT) {
                    uint32_t adl = (uint32_t)__cvta_generic_to_shared(
                        &smBl[s][(rowB0 + p * 16) * SSTW + kk * 8 + kwB]);
                    LDSM_X4(bl[p], adl);
                }
            }
            #pragma unroll
            for (int am = 0; am < 2; am++)
                #pragma unroll
                for (int p = 0; p < 2; p++) {
                    MMA_FP16(acc[am][2*p],     a[am], bh[p][0], bh[p][1]);
                    MMA_FP16(acc[am][2*p + 1], a[am], bh[p][2], bh[p][3]);
                    if constexpr (SPLIT) {
                        MMA_FP16(acc[am][2*p],     a[am], bl[p][0], bl[p][1]);
                        MMA_FP16(acc[am][2*p + 1], a[am], bl[p][2], bl[p][3]);
                    }
                }
        }
        __syncthreads();
    }

    // epilogue
    #pragma unroll
    for (int am = 0; am < 2; am++) {
        int r = row0 + wm * 32 + am * 16 + q;
        #pragma unroll
        for (int bn = 0; bn < 4; bn++) {
            int c = col0 + wn * 32 + bn * 8 + rr * 2;
            float2 v0 = {acc[am][bn][0], acc[am][bn][1]};
            float2 v1 = {acc[am][bn][2], acc[am][bn][3]};
            *(float2*)&C[(size_t)r * ldc + c]       = v0;
            *(float2*)&C[(size_t)(r + 8) * ldc + c] = v1;
        }
    }
}

// -------------------- GRU gates + scatter --------------------
// g_Gc row: [0:500)=r preact (gi+gh), [500:1000)=z preact, [1000:1500)=gi_n.
// g_Ghn row: [0:500)=gh_n.
__global__ void k_gru_scatter(const float* __restrict__ memory,
                              const float* __restrict__ bih,
                              const float* __restrict__ bhh,
                              const float* __restrict__ times,
                              const int* __restrict__ src,
                              const int* __restrict__ dst,
                              float* __restrict__ out_mem,
                              float* __restrict__ out_lu) {
    int i = blockIdx.x;
    int e = i & (BB - 1);
    int node = (i < BB) ? src[e] : dst[e];
    if (g_lastpos[node] != i) return;      // only the last message per node writes
    const float* gc   = &g_Gc [(size_t)i * NP];
    const float* ghn  = &g_Ghn[(size_t)i * KP2];
    const float* hrow = memory + (size_t)node * DM;   // exact fp32 h
    float* om = out_mem + (size_t)node * DM;
    for (int j = threadIdx.x; j < DM; j += blockDim.x) {
        float r = sigf(gc[j]      + bih[j]      + bhh[j]);
        float z = sigf(gc[DM + j] + bih[DM + j] + bhh[DM + j]);
        float n = tanhf(gc[2*DM + j] + bih[2*DM + j] + r * (ghn[j] + bhh[2*DM + j]));
        float h = hrow[j];
        om[j] = (1.0f - z) * n + z * h;
    }
    if (threadIdx.x == 0) out_lu[node] = times[e];
}

// -------------------- score MLP tail (layers 2, 3) --------------------
__global__ void k_scores_tail(const float* __restrict__ b1,
                              const float* __restrict__ W2, const float* __restrict__ b2,
                              const float* __restrict__ W3, const float* __restrict__ b3,
                              float* __restrict__ out) {
    __shared__ float sW2[80 * 10];
    __shared__ float sW3[10];
    __shared__ float sb1[80];
    __shared__ float sb2[10];
    int tid = threadIdx.x;
    if (tid < 80) sb1[tid] = b1[tid];
    if (tid >= 128 && tid < 128 + 10) { sW3[tid - 128] = W3[tid - 128]; sb2[tid - 128] = b2[tid - 128]; }
    for (int j = tid; j < 800; j += blockDim.x) sW2[j] = W2[j];
    __syncthreads();

    int i = blockIdx.x * blockDim.x + tid;    // 0..8191
    const float* h1row = &g_H1[(size_t)i * NX];
    float h1[80];
    #pragma unroll 8
    for (int j = 0; j < 80; j++) h1[j] = fmaxf(h1row[j] + sb1[j], 0.0f);
    float sc = b3[0];
    #pragma unroll
    for (int c = 0; c < 10; c++) {
        float h2 = sb2[c];
        #pragma unroll 8
        for (int j = 0; j < 80; j++) h2 = fmaf(h1[j], sW2[j * 10 + c], h2);
        sc = fmaf(fmaxf(h2, 0.0f), sW3[c], sc);
    }
    out[i] = sc;    // rows 0..B-1 = score_pos, B..2B-1 = score_neg
}

// -------------------- launcher --------------------
extern "C" void kernel_launch(void* const* d_in, const int* in_sizes, int n_in,
                              void* d_out, int out_size) {
    const float* memory      = (const float*)d_in[0];
    const float* last_update = (const float*)d_in[1];
    const float* comm_emb    = (const float*)d_in[2];
    const float* ef_table    = (const float*)d_in[3];
    const float* edge_times  = (const float*)d_in[4];
    const float* time_w      = (const float*)d_in[5];
    const float* time_b      = (const float*)d_in[6];
    const float* W_ih        = (const float*)d_in[7];
    const float* W_hh        = (const float*)d_in[8];
    const float* b_ih        = (const float*)d_in[9];
    const float* b_hh        = (const float*)d_in[10];
    const float* W1          = (const float*)d_in[11];
    const float* b1          = (const float*)d_in[12];
    const float* W2          = (const float*)d_in[13];
    const float* b2          = (const float*)d_in[14];
    const float* W3          = (const float*)d_in[15];
    const float* b3          = (const float*)d_in[16];
    const int*   src         = (const int*)d_in[17];
    const int*   dst         = (const int*)d_in[18];
    const int*   neg         = (const int*)d_in[19];
    const int*   edge_idxs   = (const int*)d_in[20];

    float* out      = (float*)d_out;
    float* out_sc   = out;                                   // score_pos[B], score_neg[B]
    float* out_mem  = out + 2 * BB;                          // new_memory [N*DM]
    float* out_lu   = out + 2 * BB + (size_t)NN * DM;        // new_last_update [N]

    // 1) copy memory -> out_mem, last_update -> out_lu
    {
        int n4 = (NN * DM) / 4;
        k_copy4<<<(n4 + 255) / 256, 256>>>((const float4*)memory, (float4*)out_mem, n4);
        int m4 = NN / 4;
        k_copy4<<<(m4 + 255) / 256, 256>>>((const float4*)last_update, (float4*)out_lu, m4);
    }
    // 2) pad/fuse/split all weights (one kernel)
    {
        int total = NP * KP1 + KP2 * KP2 + NX * KX;
        k_pad_all<<<(total + 255) / 256, 256>>>(W_ih, W_hh, W1);
    }
    // 3) build message + score-input matrices (one kernel)
    k_build<<<2 * ROWS, 256>>>(memory, last_update, ef_table, edge_times,
                               time_w, time_b, comm_emb, src, dst, neg, edge_idxs);
    // 4) last-message aggregation
    k_lp_init<<<(2 * BB + 255) / 256, 256>>>(src, dst);
    k_lp_max <<<(2 * BB + 255) / 256, 256>>>(src, dst);
    // 5) tensor-core GEMMs (operands bound in device code)
    {
        dim3 g0(NP / 64, ROWS / 128);      // (24, 64) fused Wc GEMM
        k_mma<0><<<g0, 256>>>();
        dim3 g1(KP2 / 64, ROWS / 128);     // (8, 64)  gh_n GEMM
        k_mma<1><<<g1, 256>>>();
        dim3 g2(NX / 64, ROWS / 128);      // (2, 64)  score layer-1
        k_mma<2><<<g2, 256>>>();
    }
    // 6) score MLP tail
    k_scores_tail<<<ROWS / 256, 256>>>(b1, W2, b2, W3, b3, out_sc);
    // 7) gates + scatter
    k_gru_scatter<<<ROWS, 512>>>(memory, b_ih, b_hh, edge_times, src, dst, out_mem, out_lu);
}

// round 17
// speedup vs baseline: 5.4878x; 1.1966x over previous
#include <cuda_runtime.h>
#include <cuda_fp16.h>
#include <cstdint>

// Problem constants
#define NN   200000
#define DM   500
#define BB   4096
#define MSG  1501        // 2*DM + 1 + DM
#define G3   1500        // 3*DM
#define ROWS 8192        // 2*B message rows

// Padded dims for guard-free GEMMs
#define KP1  1504        // msgs K padded (1501 -> 1504, mult of 32)
#define KP2  512         // h K padded (500 -> 512) == N of the gh_n GEMM
#define NP   1536        // fused GRU GEMM N padded (1500 -> 1536)
#define KX   2048        // score layer-1 K padded (4 segments of 512)
#define NX   128         // score layer-1 N padded (80 -> 128)

typedef __half fp16;

// -------------------- scratch (device globals, no allocation) --------------------
// ONLY referenced from device code (host-side symbol name = host shadow addr,
// silently dereferenced via ATS on GB300 — round 2-4 bug).
__device__ __align__(128) fp16 g_A1  [(size_t)ROWS * KP1];   // msgs, fp16
__device__ __align__(128) fp16 g_Wc  [(size_t)NP   * KP1];   // W_ih + fused W_hh(r,z)
__device__ __align__(128) fp16 g_Whn [(size_t)KP2  * KP2];   // W_hh n-gate rows, padded
__device__ __align__(128) fp16 g_Xp  [(size_t)ROWS * KX ];
__device__ __align__(128) fp16 g_W1ph[(size_t)NX   * KX ];
__device__ __align__(128) fp16 g_W1pl[(size_t)NX   * KX ];
__device__ __align__(128) float g_Gc [(size_t)ROWS * NP ];   // msgs @ Wc^T
__device__ __align__(128) float g_Ghn[(size_t)ROWS * KP2];   // h @ Whn^T
__device__ __align__(128) float g_H1 [(size_t)ROWS * NX ];
__device__ int g_lastpos[NN];

// -------------------- helpers --------------------
__device__ __forceinline__ float sigf(float x) { return 1.0f / (1.0f + expf(-x)); }
__device__ __forceinline__ void split_fp16(float x, fp16* ph, fp16* pl) {
    fp16 h = __float2half_rn(x);
    fp16 l = __float2half_rn(x - __half2float(h));
    *ph = h; *pl = l;
}
__device__ __forceinline__ uint32_t h2u(float lo, float hi) {
    __half2 h = __floats2half2_rn(lo, hi);
    return *(uint32_t*)&h;
}

// -------------------- copy kernel (small arrays) --------------------
__global__ void k_copy4(const float4* __restrict__ src, float4* __restrict__ dst, int n4) {
    int i = blockIdx.x * blockDim.x + threadIdx.x;
    if (i < n4) dst[i] = src[i];
}

// -------------------- weight prep (Wc, Whn, W1 split) — one kernel --------------------
__global__ void k_pad_all(const float* __restrict__ Wih, const float* __restrict__ Whh,
                          const float* __restrict__ W1) {
    const int total1 = NP * KP1;
    const int total2 = KP2 * KP2;
    const int total3 = NX * KX;
    int idx = blockIdx.x * blockDim.x + threadIdx.x;
    if (idx < total1) {
        int r = idx / KP1, k = idx - r * KP1;
        float v = 0.0f;
        if (r < G3 && k < MSG) v = Wih[r * MSG + k];
        if (r < 2 * DM && k < DM) v += Whh[r * DM + k];
        g_Wc[idx] = __float2half_rn(v);
    } else if (idx < total1 + total2) {
        int j = idx - total1;
        int n = j >> 9, k = j & (KP2 - 1);
        float v = (n < DM && k < DM) ? Whh[(2 * DM + n) * DM + k] : 0.0f;
        g_Whn[j] = __float2half_rn(v);
    } else if (idx < total1 + total2 + total3) {
        int j = idx - total1 - total2;
        int n = j >> 11, k = j & (KX - 1);
        int seg = k >> 9, kk = k & 511;
        float v = 0.0f;
        if (n < 80 && kk < DM) v = W1[(seg * DM + kk) * 80 + n];
        split_fp16(v, &g_W1ph[j], &g_W1pl[j]);
    }
}

// -------------------- build message + score-input matrices (vectorized) --------------------
__global__ void k_build(const float* __restrict__ memory,
                        const float* __restrict__ last_update,
                        const float* __restrict__ ef_table,
                        const float* __restrict__ times,
                        const float* __restrict__ time_w,
                        const float* __restrict__ time_b,
                        const float* __restrict__ ce,
                        const int* __restrict__ src,
                        const int* __restrict__ dst,
                        const int* __restrict__ neg,
                        const int* __restrict__ edge_idxs) {
    int blk = blockIdx.x;
    int t = threadIdx.x;
    if (blk < ROWS) {
        // ---- message row: [ma(500), mb(500), ef(1), enc(500), pad(3)] ----
        int i = blk;
        int eg = i & (BB - 1);
        bool srow = (i < BB);
        int a = srow ? src[eg] : dst[eg];
        int b = srow ? dst[eg] : src[eg];
        float tt = times[eg];
        float dt = tt - last_update[a];
        size_t ro = (size_t)i * KP1;
        const float* ma = memory + (size_t)a * DM;
        const float* mb = memory + (size_t)b * DM;
        if (t < 250) {
            *(uint32_t*)&g_A1[ro + 2*t]      = h2u(ma[2*t], ma[2*t+1]);
            *(uint32_t*)&g_A1[ro + DM + 2*t] = h2u(mb[2*t], mb[2*t+1]);
        }
        if (t < 249) {                       // enc pairs (1,2),(3,4),...,(497,498)
            int j = 2*t + 1;
            float e0 = cosf(fmaf(dt, time_w[j],     time_b[j]));
            float e1 = cosf(fmaf(dt, time_w[j + 1], time_b[j + 1]));
            *(uint32_t*)&g_A1[ro + 1001 + j] = h2u(e0, e1);
        } else if (t == 249) {               // enc[499] + zero pads
            float e0 = cosf(fmaf(dt, time_w[499], time_b[499]));
            *(uint32_t*)&g_A1[ro + 1500] = h2u(e0, 0.0f);
            *(uint32_t*)&g_A1[ro + 1502] = 0u;
        } else if (t == 250) {               // (ef, enc[0]) at 1000
            float ef = ef_table[edge_idxs[eg]];
            float e0 = cosf(fmaf(dt, time_w[0], time_b[0]));
            *(uint32_t*)&g_A1[ro + 1000] = h2u(ef, e0);
        }
    } else {
        // ---- score MLP input row: 4 segments of 512 (500 data + 12 pad) ----
        int i = blk - ROWS;
        int eg = i & (BB - 1);
        int s = src[eg];
        int o = (i < BB) ? dst[eg] : neg[eg];
        size_t ro = (size_t)i * KX;
        const float* segp[4] = { memory + (size_t)s * DM, ce + (size_t)s * DM,
                                 memory + (size_t)o * DM, ce + (size_t)o * DM };
        int k0 = 8 * t;                      // 8 elements per thread, one segment
        const float* p = segp[k0 >> 9];
        int jb = k0 & 511;
        uint32_t w[4];
        #pragma unroll
        for (int u = 0; u < 4; u++) {
            int j = jb + 2*u;
            float v0 = (j     < DM) ? p[j]     : 0.0f;
            float v1 = (j + 1 < DM) ? p[j + 1] : 0.0f;
            w[u] = h2u(v0, v1);
        }
        *(uint4*)&g_Xp[ro + k0] = make_uint4(w[0], w[1], w[2], w[3]);
    }
}

// -------------------- last-message aggregation --------------------
__global__ void k_lp_init(const int* __restrict__ src, const int* __restrict__ dst) {
    int i = blockIdx.x * blockDim.x + threadIdx.x;
    if (i >= 2 * BB) return;
    int node = (i < BB) ? src[i] : dst[i - BB];
    g_lastpos[node] = -1;
}
__global__ void k_lp_max(const int* __restrict__ src, const int* __restrict__ dst) {
    int i = blockIdx.x * blockDim.x + threadIdx.x;
    if (i >= 2 * BB) return;
    int node = (i < BB) ? src[i] : dst[i - BB];
    atomicMax(&g_lastpos[node], i);
}

// -------------------- fp16 tensor-core GEMM: C = A @ B^T --------------------
// MODE 0: g_Gc  = g_A1 @ g_Wc^T            (K=1504, N=1536, 3-stage)
//         + CPY extra grid.y rows of copy blocks (memory -> out_mem overlap)
// MODE 1: g_Ghn = g_A1[:, :512] @ g_Whn^T  (K=512,  N=512,  3-stage)
// MODE 2: g_H1  = g_Xp @ (g_W1ph+g_W1pl)^T (K=2048, N=128,  split 2-product, 2-stage)
// BM=128, BN=64, BK=32, 256 threads, cp.async pipeline, ldmatrix.x4 + mma.m16n8k16.f16.
#define SSTW 20                  // smem row stride in words (16 data + 4 pad)
#define CPY  12                  // copy grid.y rows prepended to MODE 0

#define MMA_FP16(ACC, A_, B0, B1) \
    asm volatile("mma.sync.aligned.m16n8k16.row.col.f32.f16.f16.f32 " \
        "{%0,%1,%2,%3}, {%4,%5,%6,%7}, {%8,%9}, {%0,%1,%2,%3};" \
        : "+f"((ACC)[0]), "+f"((ACC)[1]), "+f"((ACC)[2]), "+f"((ACC)[3]) \
        : "r"((A_)[0]), "r"((A_)[1]), "r"((A_)[2]), "r"((A_)[3]), \
          "r"(B0), "r"(B1))

#define LDSM_X4(R, ADDR) \
    asm volatile("ldmatrix.sync.aligned.m8n8.x4.shared.b16 {%0,%1,%2,%3}, [%4];" \
        : "=r"((R)[0]), "=r"((R)[1]), "=r"((R)[2]), "=r"((R)[3]) : "r"(ADDR))

template <int MODE>
__global__ void __launch_bounds__(256) k_mma(const float4* __restrict__ cpsrc,
                                             float4* __restrict__ cpdst, int n4) {
    // ---- fused copy blocks (MODE 0 only, scheduled first in raster order) ----
    if (MODE == 0 && blockIdx.y < CPY) {
        int cb  = blockIdx.y * gridDim.x + blockIdx.x;     // 0 .. CPY*24-1
        int nth = CPY * gridDim.x * blockDim.x;
        #pragma unroll 4
        for (int i = cb * blockDim.x + threadIdx.x; i < n4; i += nth)
            cpdst[i] = cpsrc[i];
        return;
    }

    constexpr bool SPLIT = (MODE == 2);
    constexpr int  ST    = SPLIT ? 2 : 3;    // pipeline stages (smem budget)
    const fp16* __restrict__ A  = (MODE == 2) ? g_Xp : g_A1;
    const int lda               = (MODE == 2) ? KX : KP1;
    const fp16* __restrict__ Bh = (MODE == 0) ? g_Wc : (MODE == 1) ? g_Whn : g_W1ph;
    const fp16* __restrict__ Bl = g_W1pl;                       // used only when SPLIT
    const int ldb               = (MODE == 0) ? KP1 : (MODE == 1) ? KP2 : KX;
    float* __restrict__ C       = (MODE == 0) ? g_Gc : (MODE == 1) ? g_Ghn : g_H1;
    const int ldc               = (MODE == 0) ? NP : (MODE == 1) ? KP2 : NX;
    const int K                 = ldb;   // B is [N x K] with row stride == K

    __shared__ __align__(16) uint32_t smA [ST][128 * SSTW];                 // 10 KB/stage
    __shared__ __align__(16) uint32_t smBh[ST][ 64 * SSTW];                 // 5 KB/stage
    __shared__ __align__(16) uint32_t smBl[SPLIT ? ST : 1][SPLIT ? 64 * SSTW : 4];

    const int tid  = threadIdx.x;
    const int lane = tid & 31;
    const int wid  = tid >> 5;          // 0..7
    const int wm   = wid >> 1;          // 0..3 -> 32-row slice of 128
    const int wn   = wid & 1;           // 0..1 -> 32-col slice of 64
    const int q    = lane >> 2;         // 0..7
    const int rr   = lane & 3;          // 0..3

    const int row0 = ((MODE == 0) ? (blockIdx.y - CPY) : blockIdx.y) * 128;
    const int col0 = blockIdx.x * 64;

    // ldmatrix per-lane source mapping
    const int rowA0 = wm * 32 + (lane & 15);                    // + am*16
    const int kwA   = (lane >> 4) << 2;                         // + kk*8
    const int rowB0 = wn * 32 + ((lane >> 4) << 3) + (lane & 7);// + p*16
    const int kwB   = ((lane >> 3) & 1) << 2;                   // + kk*8

    float acc[2][4][4];
    #pragma unroll
    for (int am = 0; am < 2; am++)
        #pragma unroll
        for (int bn = 0; bn < 4; bn++)
            #pragma unroll
            for (int c = 0; c < 4; c++) acc[am][bn][c] = 0.0f;

    const int K_tiles = K >> 5;

    auto load_stage = [&](int stage, int k0) {
        // A tile: 128 rows x 32 fp16 = 512 x 16B chunks; 256 thr -> 2 each
        #pragma unroll
        for (int i = 0; i < 2; i++) {
            int f  = i * 256 + tid;      // 0..511
            int r  = f >> 2;             // 0..127
            int w4 = (f & 3) * 4;        // word offset 0,4,8,12
            const fp16* gp = A + (size_t)(row0 + r) * lda + k0 + w4 * 2;
            uint32_t sp = (uint32_t)__cvta_generic_to_shared(&smA[stage][r * SSTW + w4]);
            asm volatile("cp.async.cg.shared.global [%0], [%1], 16;" :: "r"(sp), "l"(gp));
        }
        // B tiles: 64 rows x 32 fp16 = 256 chunks each
        {
            int r  = tid >> 2;           // 0..63
            int w4 = (tid & 3) * 4;
            int eo = k0 + w4 * 2;
            const fp16* gph = Bh + (size_t)(col0 + r) * ldb + eo;
            uint32_t sph = (uint32_t)__cvta_generic_to_shared(&smBh[stage][r * SSTW + w4]);
            asm volatile("cp.async.cg.shared.global [%0], [%1], 16;" :: "r"(sph), "l"(gph));
            if constexpr (SPLIT) {
                const fp16* gpl = Bl + (size_t)(col0 + r) * ldb + eo;
                uint32_t spl = (uint32_t)__cvta_generic_to_shared(&smBl[stage][r * SSTW + w4]);
                asm volatile("cp.async.cg.shared.global [%0], [%1], 16;" :: "r"(spl), "l"(gpl));
            }
        }
        asm volatile("cp.async.commit_group;");
    };

    // prologue: ST-1 stage loads (empty commit when out of range)
    #pragma unroll
    for (int p = 0; p < ST - 1; p++) {
        if (p < K_tiles) load_stage(p, p << 5);
        else             asm volatile("cp.async.commit_group;");
    }

    for (int t = 0; t < K_tiles; t++) {
        if (t + ST - 1 < K_tiles) load_stage((t + ST - 1) % ST, (t + ST - 1) << 5);
        else                      asm volatile("cp.async.commit_group;");
        if constexpr (ST == 3) asm volatile("cp.async.wait_group 2;");
        else                   asm volatile("cp.async.wait_group 1;");
        __syncthreads();

        const int s = t % ST;

        #pragma unroll
        for (int kk = 0; kk < 2; kk++) {            // two k16 steps per 32-elem tile
            uint32_t a[2][4], bh[2][4], bl[2][4];
            #pragma unroll
            for (int am = 0; am < 2; am++) {
                uint32_t ad = (uint32_t)__cvta_generic_to_shared(
                    &smA[s][(rowA0 + am * 16) * SSTW + kk * 8 + kwA]);
                LDSM_X4(a[am], ad);
            }
            #pragma unroll
            for (int p = 0; p < 2; p++) {
                uint32_t ad = (uint32_t)__cvta_generic_to_shared(
                    &smBh[s][(rowB0 + p * 16) * SSTW + kk * 8 + kwB]);
                LDSM_X4(bh[p], ad);
                if constexpr (SPLIT) {
                    uint32_t adl = (uint32_t)__cvta_generic_to_shared(
                        &smBl[s][(rowB0 + p * 16) * SSTW + kk * 8 + kwB]);
                    LDSM_X4(bl[p], adl);
                }
            }
            #pragma unroll
            for (int am = 0; am < 2; am++)
                #pragma unroll
                for (int p = 0; p < 2; p++) {
                    MMA_FP16(acc[am][2*p],     a[am], bh[p][0], bh[p][1]);
                    MMA_FP16(acc[am][2*p + 1], a[am], bh[p][2], bh[p][3]);
                    if constexpr (SPLIT) {
                        MMA_FP16(acc[am][2*p],     a[am], bl[p][0], bl[p][1]);
                        MMA_FP16(acc[am][2*p + 1], a[am], bl[p][2], bl[p][3]);
                    }
                }
        }
        __syncthreads();
    }

    // epilogue
    #pragma unroll
    for (int am = 0; am < 2; am++) {
        int r = row0 + wm * 32 + am * 16 + q;
        #pragma unroll
        for (int bn = 0; bn < 4; bn++) {
            int c = col0 + wn * 32 + bn * 8 + rr * 2;
            float2 v0 = {acc[am][bn][0], acc[am][bn][1]};
            float2 v1 = {acc[am][bn][2], acc[am][bn][3]};
            *(float2*)&C[(size_t)r * ldc + c]       = v0;
            *(float2*)&C[(size_t)(r + 8) * ldc + c] = v1;
        }
    }
}

// -------------------- GRU gates + scatter --------------------
// g_Gc row: [0:500)=r preact (gi+gh), [500:1000)=z preact, [1000:1500)=gi_n.
// g_Ghn row: [0:500)=gh_n.
__global__ void k_gru_scatter(const float* __restrict__ memory,
                              const float* __restrict__ bih,
                              const float* __restrict__ bhh,
                              const float* __restrict__ times,
                              const int* __restrict__ src,
                              const int* __restrict__ dst,
                              float* __restrict__ out_mem,
                              float* __restrict__ out_lu) {
    int i = blockIdx.x;
    int e = i & (BB - 1);
    int node = (i < BB) ? src[e] : dst[e];
    if (g_lastpos[node] != i) return;      // only the last message per node writes
    const float* gc   = &g_Gc [(size_t)i * NP];
    const float* ghn  = &g_Ghn[(size_t)i * KP2];
    const float* hrow = memory + (size_t)node * DM;   // exact fp32 h
    float* om = out_mem + (size_t)node * DM;
    for (int j = threadIdx.x; j < DM; j += blockDim.x) {
        float r = sigf(gc[j]      + bih[j]      + bhh[j]);
        float z = sigf(gc[DM + j] + bih[DM + j] + bhh[DM + j]);
        float n = tanhf(gc[2*DM + j] + bih[2*DM + j] + r * (ghn[j] + bhh[2*DM + j]));
        float h = hrow[j];
        om[j] = (1.0f - z) * n + z * h;
    }
    if (threadIdx.x == 0) out_lu[node] = times[e];
}

// -------------------- score MLP tail (layers 2, 3) --------------------
__global__ void k_scores_tail(const float* __restrict__ b1,
                              const float* __restrict__ W2, const float* __restrict__ b2,
                              const float* __restrict__ W3, const float* __restrict__ b3,
                              float* __restrict__ out) {
    __shared__ float sW2[80 * 10];
    __shared__ float sW3[10];
    __shared__ float sb1[80];
    __shared__ float sb2[10];
    int tid = threadIdx.x;
    if (tid < 80) sb1[tid] = b1[tid];
    if (tid >= 128 && tid < 128 + 10) { sW3[tid - 128] = W3[tid - 128]; sb2[tid - 128] = b2[tid - 128]; }
    for (int j = tid; j < 800; j += blockDim.x) sW2[j] = W2[j];
    __syncthreads();

    int i = blockIdx.x * blockDim.x + tid;    // 0..8191
    const float* h1row = &g_H1[(size_t)i * NX];
    float h1[80];
    #pragma unroll 8
    for (int j = 0; j < 80; j++) h1[j] = fmaxf(h1row[j] + sb1[j], 0.0f);
    float sc = b3[0];
    #pragma unroll
    for (int c = 0; c < 10; c++) {
        float h2 = sb2[c];
        #pragma unroll 8
        for (int j = 0; j < 80; j++) h2 = fmaf(h1[j], sW2[j * 10 + c], h2);
        sc = fmaf(fmaxf(h2, 0.0f), sW3[c], sc);
    }
    out[i] = sc;    // rows 0..B-1 = score_pos, B..2B-1 = score_neg
}

// -------------------- launcher --------------------
extern "C" void kernel_launch(void* const* d_in, const int* in_sizes, int n_in,
                              void* d_out, int out_size) {
    const float* memory      = (const float*)d_in[0];
    const float* last_update = (const float*)d_in[1];
    const float* comm_emb    = (const float*)d_in[2];
    const float* ef_table    = (const float*)d_in[3];
    const float* edge_times  = (const float*)d_in[4];
    const float* time_w      = (const float*)d_in[5];
    const float* time_b      = (const float*)d_in[6];
    const float* W_ih        = (const float*)d_in[7];
    const float* W_hh        = (const float*)d_in[8];
    const float* b_ih        = (const float*)d_in[9];
    const float* b_hh        = (const float*)d_in[10];
    const float* W1          = (const float*)d_in[11];
    const float* b1          = (const float*)d_in[12];
    const float* W2          = (const float*)d_in[13];
    const float* b2          = (const float*)d_in[14];
    const float* W3          = (const float*)d_in[15];
    const float* b3          = (const float*)d_in[16];
    const int*   src         = (const int*)d_in[17];
    const int*   dst         = (const int*)d_in[18];
    const int*   neg         = (const int*)d_in[19];
    const int*   edge_idxs   = (const int*)d_in[20];

    float* out      = (float*)d_out;
    float* out_sc   = out;                                   // score_pos[B], score_neg[B]
    float* out_mem  = out + 2 * BB;                          // new_memory [N*DM]
    float* out_lu   = out + 2 * BB + (size_t)NN * DM;        // new_last_update [N]

    // 1) small copy: last_update -> out_lu (big memory copy fused into k_mma<0>)
    {
        int m4 = NN / 4;
        k_copy4<<<(m4 + 255) / 256, 256>>>((const float4*)last_update, (float4*)out_lu, m4);
    }
    // 2) pad/fuse/split all weights (one kernel)
    {
        int total = NP * KP1 + KP2 * KP2 + NX * KX;
        k_pad_all<<<(total + 255) / 256, 256>>>(W_ih, W_hh, W1);
    }
    // 3) build message + score-input matrices (one kernel, vectorized)
    k_build<<<2 * ROWS, 256>>>(memory, last_update, ef_table, edge_times,
                               time_w, time_b, comm_emb, src, dst, neg, edge_idxs);
    // 4) last-message aggregation
    k_lp_init<<<(2 * BB + 255) / 256, 256>>>(src, dst);
    k_lp_max <<<(2 * BB + 255) / 256, 256>>>(src, dst);
    // 5) tensor-core GEMMs (scratch operands bound in device code)
    {
        int n4 = (NN * DM) / 4;                  // fused output-memory copy work
        dim3 g0(NP / 64, ROWS / 128 + CPY);      // (24, 64+12): copy rows first
        k_mma<0><<<g0, 256>>>((const float4*)memory, (float4*)out_mem, n4);
        dim3 g1(KP2 / 64, ROWS / 128);           // (8, 64)  gh_n GEMM
        k_mma<1><<<g1, 256>>>(nullptr, nullptr, 0);
        dim3 g2(NX / 64, ROWS / 128);            // (2, 64)  score layer-1
        k_mma<2><<<g2, 256>>>(nullptr, nullptr, 0);
    }
    // 6) score MLP tail
    k_scores_tail<<<ROWS / 256, 256>>>(b1, W2, b2, W3, b3, out_sc);
    // 7) gates + scatter
    k_gru_scatter<<<ROWS, 512>>>(memory, b_ih, b_hh, edge_times, src, dst, out_mem, out_lu);
}